// round 2
// baseline (speedup 1.0000x reference)
#include <cuda_runtime.h>

#define Bsz 16384
#define INF 512
#define H1D 512
#define H2D 256
#define NO 4
#define NT 4
#define EPSV 1e-5f

// Scratch: h[o][b][h1] fp32 (134 MB), routing lists, counters.
__device__ float g_h[(size_t)NO * Bsz * H1D];
__device__ int   g_list[NT * Bsz];
__device__ int   g_count[NT];

__device__ __forceinline__ void cp_async16(void* smem, const void* gmem) {
    unsigned s = (unsigned)__cvta_generic_to_shared(smem);
    asm volatile("cp.async.ca.shared.global [%0], [%1], 16;" :: "r"(s), "l"(gmem));
}
__device__ __forceinline__ void cp_commit() { asm volatile("cp.async.commit_group;"); }
template <int N>
__device__ __forceinline__ void cp_wait() { asm volatile("cp.async.wait_group %0;" :: "n"(N)); }

// ---------------------------------------------------------------------------
// Routing: bucket sample ids by treatment.
// ---------------------------------------------------------------------------
__global__ void zero_counts_kernel() {
    if (threadIdx.x < NT) g_count[threadIdx.x] = 0;
}

__global__ void route_kernel(const int* __restrict__ treatment) {
    int b = blockIdx.x * blockDim.x + threadIdx.x;
    if (b < Bsz) {
        int t = treatment[b];
        int p = atomicAdd(&g_count[t], 1);
        g_list[t * Bsz + p] = b;
    }
}

// ---------------------------------------------------------------------------
// Stage 1: h[o] = BN1(relu(feature @ W1[o] + b1[o]))
// Tile 128x128, K-chunk 16, 256 threads, 8x8 per-thread micro-tile.
// ---------------------------------------------------------------------------
__global__ void __launch_bounds__(256) stage1_kernel(
    const float* __restrict__ feat, const float* __restrict__ W1,
    const float* __restrict__ b1, const float* __restrict__ g1,
    const float* __restrict__ be1, const float* __restrict__ m1,
    const float* __restrict__ v1)
{
    const int o  = blockIdx.z;
    const int m0 = blockIdx.y * 128;
    const int n0 = blockIdx.x * 128;

    __shared__ __align__(16) float As[2][16][132];  // [k][m], padded
    __shared__ __align__(16) float Bs[2][16][128];  // [k][n]

    const int tid = threadIdx.x;
    const int tm  = tid >> 4;   // 0..15
    const int tn  = tid & 15;   // 0..15

    float acc[8][8];
#pragma unroll
    for (int i = 0; i < 8; i++)
#pragma unroll
        for (int j = 0; j < 8; j++) acc[i][j] = 0.f;

    const float* Aptr = feat + (size_t)m0 * INF;
    const float* Bptr = W1 + (size_t)o * INF * H1D + n0;

    auto load_tile = [&](int k0, int bufi) {
#pragma unroll
        for (int i = 0; i < 2; i++) {
            int id = tid + i * 256;
            // A: 128 rows x 16 k = 512 float4
            int r  = id >> 2;
            int c4 = (id & 3) << 2;
            float4 a = *reinterpret_cast<const float4*>(Aptr + (size_t)r * INF + k0 + c4);
            As[bufi][c4 + 0][r] = a.x;
            As[bufi][c4 + 1][r] = a.y;
            As[bufi][c4 + 2][r] = a.z;
            As[bufi][c4 + 3][r] = a.w;
            // B: 16 k x 128 n = 512 float4 via cp.async
            int kk = id >> 5;
            int n4 = (id & 31) << 2;
            cp_async16(&Bs[bufi][kk][n4], Bptr + (size_t)(k0 + kk) * H1D + n4);
        }
        cp_commit();
    };

    load_tile(0, 0);
    int buf = 0;
    for (int k0 = 0; k0 < INF; k0 += 16) {
        bool has_next = (k0 + 16) < INF;
        if (has_next) load_tile(k0 + 16, buf ^ 1);
        if (has_next) cp_wait<1>(); else cp_wait<0>();
        __syncthreads();
#pragma unroll
        for (int kk = 0; kk < 16; kk++) {
            float af[8], bf[8];
            *reinterpret_cast<float4*>(&af[0]) = *reinterpret_cast<const float4*>(&As[buf][kk][tm * 8]);
            *reinterpret_cast<float4*>(&af[4]) = *reinterpret_cast<const float4*>(&As[buf][kk][tm * 8 + 4]);
            *reinterpret_cast<float4*>(&bf[0]) = *reinterpret_cast<const float4*>(&Bs[buf][kk][tn * 8]);
            *reinterpret_cast<float4*>(&bf[4]) = *reinterpret_cast<const float4*>(&Bs[buf][kk][tn * 8 + 4]);
#pragma unroll
            for (int i = 0; i < 8; i++)
#pragma unroll
                for (int j = 0; j < 8; j++) acc[i][j] = fmaf(af[i], bf[j], acc[i][j]);
        }
        __syncthreads();
        buf ^= 1;
    }

    // Epilogue: +b1, relu, BN1 affine, store h fp32.
    const int colbase = n0 + tn * 8;
    float sc[8], sh[8], bb[8];
#pragma unroll
    for (int j = 0; j < 8; j++) {
        int idx = o * H1D + colbase + j;
        float s = g1[idx] * rsqrtf(v1[idx] + EPSV);
        sc[j] = s;
        sh[j] = be1[idx] - m1[idx] * s;
        bb[j] = b1[idx];
    }
#pragma unroll
    for (int i = 0; i < 8; i++) {
        int row = m0 + tm * 8 + i;
        float outv[8];
#pragma unroll
        for (int j = 0; j < 8; j++) {
            float h = acc[i][j] + bb[j];
            h = fmaxf(h, 0.f);
            outv[j] = h * sc[j] + sh[j];
        }
        float* dst = &g_h[((size_t)o * Bsz + row) * H1D + colbase];
        *reinterpret_cast<float4*>(dst)     = *reinterpret_cast<float4*>(&outv[0]);
        *reinterpret_cast<float4*>(dst + 4) = *reinterpret_cast<float4*>(&outv[4]);
    }
}

// ---------------------------------------------------------------------------
// Stage 2+3: for each (o,t) bucket, z = BN2(relu(h_rows @ W2[o,t] + b2)),
// pred = z . W3[o,t] + b3, scatter to out[b][o].
// Tile 128x256 (full H2 per CTA), K-chunk 8, 512 threads, 8x8 per thread.
// Rows gathered via g_list.
// ---------------------------------------------------------------------------
__global__ void __launch_bounds__(512) stage2_kernel(
    const float* __restrict__ W2, const float* __restrict__ b2,
    const float* __restrict__ g2, const float* __restrict__ be2,
    const float* __restrict__ m2, const float* __restrict__ v2,
    const float* __restrict__ W3, const float* __restrict__ b3,
    float* __restrict__ out)
{
    const int o = blockIdx.z, t = blockIdx.y;
    const int cnt = g_count[t];
    const int m0 = blockIdx.x * 128;
    if (m0 >= cnt) return;

    __shared__ __align__(16) float As[2][8][132];   // [k][m]
    __shared__ __align__(16) float Bs[2][8][256];   // [k][n]
    __shared__ int gidx[128];

    const int tid = threadIdx.x;
    if (tid < 128) {
        int r = m0 + tid;
        gidx[tid] = g_list[t * Bsz + (r < cnt ? r : cnt - 1)];
    }
    __syncthreads();

    const int tm = tid >> 5;   // 0..15 -> rows (warp-uniform)
    const int tn = tid & 31;   // 0..31 -> cols

    float acc[8][8];
#pragma unroll
    for (int i = 0; i < 8; i++)
#pragma unroll
        for (int j = 0; j < 8; j++) acc[i][j] = 0.f;

    const float* hbase = g_h + (size_t)o * Bsz * H1D;
    const float* Bptr  = W2 + ((size_t)(o * NT + t) * H1D) * H2D;

    auto load_tile = [&](int k0, int bufi) {
        if (tid < 256) {
            // A: 128 rows x 8 k = 256 float4, gathered rows
            int r  = tid >> 1;
            int c4 = (tid & 1) << 2;
            const float* p = hbase + (size_t)gidx[r] * H1D + k0 + c4;
            float4 a = *reinterpret_cast<const float4*>(p);
            As[bufi][c4 + 0][r] = a.x;
            As[bufi][c4 + 1][r] = a.y;
            As[bufi][c4 + 2][r] = a.z;
            As[bufi][c4 + 3][r] = a.w;
        }
        // B: 8 k x 256 n = 512 float4 via cp.async
        int kk = tid >> 6;
        int n4 = (tid & 63) << 2;
        cp_async16(&Bs[bufi][kk][n4], Bptr + (size_t)(k0 + kk) * H2D + n4);
        cp_commit();
    };

    load_tile(0, 0);
    int buf = 0;
    for (int k0 = 0; k0 < H1D; k0 += 8) {
        bool has_next = (k0 + 8) < H1D;
        if (has_next) load_tile(k0 + 8, buf ^ 1);
        if (has_next) cp_wait<1>(); else cp_wait<0>();
        __syncthreads();
#pragma unroll
        for (int kk = 0; kk < 8; kk++) {
            float af[8], bf[8];
            *reinterpret_cast<float4*>(&af[0]) = *reinterpret_cast<const float4*>(&As[buf][kk][tm * 8]);
            *reinterpret_cast<float4*>(&af[4]) = *reinterpret_cast<const float4*>(&As[buf][kk][tm * 8 + 4]);
            *reinterpret_cast<float4*>(&bf[0]) = *reinterpret_cast<const float4*>(&Bs[buf][kk][tn * 8]);
            *reinterpret_cast<float4*>(&bf[4]) = *reinterpret_cast<const float4*>(&Bs[buf][kk][tn * 8 + 4]);
#pragma unroll
            for (int i = 0; i < 8; i++)
#pragma unroll
                for (int j = 0; j < 8; j++) acc[i][j] = fmaf(af[i], bf[j], acc[i][j]);
        }
        __syncthreads();
        buf ^= 1;
    }

    // Epilogue: +b2, relu, BN2 affine, dot with W3, warp-reduce over the 32
    // column-lanes (one warp == one tm == 8 rows x full 256 cols), scatter.
    const int head = o * NT + t;
    float sc[8], sh[8], bb[8], w3[8];
#pragma unroll
    for (int j = 0; j < 8; j++) {
        int idx = head * H2D + tn * 8 + j;
        float s = g2[idx] * rsqrtf(v2[idx] + EPSV);
        sc[j] = s;
        sh[j] = be2[idx] - m2[idx] * s;
        bb[j] = b2[idx];
        w3[j] = W3[idx];
    }
    const float bias3 = b3[head];
#pragma unroll
    for (int i = 0; i < 8; i++) {
        float partial = 0.f;
#pragma unroll
        for (int j = 0; j < 8; j++) {
            float z = acc[i][j] + bb[j];
            z = fmaxf(z, 0.f);
            z = z * sc[j] + sh[j];
            partial = fmaf(z, w3[j], partial);
        }
#pragma unroll
        for (int off = 16; off > 0; off >>= 1)
            partial += __shfl_xor_sync(0xffffffffu, partial, off);
        if (tn == 0) {
            int rlocal = tm * 8 + i;
            if (m0 + rlocal < cnt) {
                int b = gidx[rlocal];
                out[(size_t)b * NO + o] = partial + bias3;
            }
        }
    }
}

// ---------------------------------------------------------------------------
extern "C" void kernel_launch(void* const* d_in, const int* in_sizes, int n_in,
                              void* d_out, int out_size)
{
    const float* feature   = (const float*)d_in[0];
    const int*   treatment = (const int*)  d_in[1];
    const float* W1  = (const float*)d_in[2];
    const float* b1  = (const float*)d_in[3];
    const float* g1  = (const float*)d_in[4];
    const float* be1 = (const float*)d_in[5];
    const float* m1  = (const float*)d_in[6];
    const float* v1  = (const float*)d_in[7];
    const float* W2  = (const float*)d_in[8];
    const float* b2  = (const float*)d_in[9];
    const float* g2  = (const float*)d_in[10];
    const float* be2 = (const float*)d_in[11];
    const float* m2  = (const float*)d_in[12];
    const float* v2  = (const float*)d_in[13];
    const float* W3  = (const float*)d_in[14];
    const float* b3  = (const float*)d_in[15];
    float* out = (float*)d_out;

    zero_counts_kernel<<<1, 32>>>();
    route_kernel<<<Bsz / 256, 256>>>(treatment);
    stage1_kernel<<<dim3(H1D / 128, Bsz / 128, NO), 256>>>(feature, W1, b1, g1, be1, m1, v1);
    stage2_kernel<<<dim3(Bsz / 128, NT, NO), 512>>>(W2, b2, g2, be2, m2, v2, W3, b3, out);
}

// round 9
// speedup vs baseline: 1.1364x; 1.1364x over previous
#include <cuda_runtime.h>
#include <stdint.h>

#define Bsz 16384
#define INF 512
#define H1D 512
#define H2D 256
#define NO 4
#define NT 4
#define EPSV 1e-5f

// Scratch (same class/size as the round-2 kernel that passed with delta=0)
__device__ float g_h[(size_t)NO * Bsz * H1D];   // 128 MiB
__device__ float g_part[(size_t)NO * 2 * Bsz];  // 512 KiB [o*2+nh][b]
__device__ int   g_list[NT * Bsz];
__device__ int   g_count[NT];

__device__ __forceinline__ void cp_async16(void* smem, const void* gmem) {
    unsigned s = (unsigned)__cvta_generic_to_shared(smem);
    asm volatile("cp.async.ca.shared.global [%0], [%1], 16;" :: "r"(s), "l"(gmem));
}
__device__ __forceinline__ void cp_commit() { asm volatile("cp.async.commit_group;"); }
template <int N>
__device__ __forceinline__ void cp_wait() { asm volatile("cp.async.wait_group %0;" :: "n"(N)); }

// ---------------------------------------------------------------------------
__global__ void zero_counts_kernel() {
    if (threadIdx.x < NT) g_count[threadIdx.x] = 0;
}
__global__ void route_kernel(const int* __restrict__ treatment) {
    int b = blockIdx.x * blockDim.x + threadIdx.x;
    if (b < Bsz) {
        int t = treatment[b];
        int p = atomicAdd(&g_count[t], 1);
        g_list[t * Bsz + p] = b;
    }
}
// out[b][o] = g_part[o*2+0][b] + g_part[o*2+1][b] + b3[o][t[b]]  (fixed order)
__global__ void combine_kernel(const int* __restrict__ treatment,
                               const float* __restrict__ b3,
                               float* __restrict__ out) {
    int i = blockIdx.x * 256 + threadIdx.x;   // i = b*NO + o
    int o = i & 3, b = i >> 2;
    int t = treatment[b];
    out[i] = g_part[(size_t)(o * 2 + 0) * Bsz + b]
           + g_part[(size_t)(o * 2 + 1) * Bsz + b]
           + b3[o * NT + t];
}

// ---------------------------------------------------------------------------
// Stage 1: h[o] = BN1(relu(feature @ W1[o] + b1))
// CTA 128x128, 256 threads (16x16 grid, 8x8 micro), K=512 in 32 blocks of 16.
// B (W1 slice) double-buffered via cp.async; A pipelined via register staging.
// ---------------------------------------------------------------------------
__global__ void __launch_bounds__(256, 2) stage1_kernel(
    const float* __restrict__ feat, const float* __restrict__ W1,
    const float* __restrict__ b1, const float* __restrict__ g1,
    const float* __restrict__ be1, const float* __restrict__ m1,
    const float* __restrict__ v1)
{
    __shared__ __align__(16) float As[2][16][132];  // [k][m]
    __shared__ __align__(16) float Bs[2][16][132];  // [k][n]

    const int tid = threadIdx.x;
    const int tm = tid >> 4, tn = tid & 15;
    const int o = blockIdx.z, m0 = blockIdx.y * 128, n0 = blockIdx.x * 128;

    const float* aSrc = feat + (size_t)m0 * INF;
    const float* bSrc = W1 + (size_t)o * INF * H1D + n0;

    const int lr0 = tid >> 2;             // A row handled by this thread (pass 0)
    const int lr1 = 64 + lr0;             // pass 1
    const int lc4 = (tid & 3) * 4;        // k-offset (floats) within block

    float4 aReg0, aReg1;
    // prologue: A for kb=0,1 ; B for kb=0,1
    aReg0 = *reinterpret_cast<const float4*>(aSrc + (size_t)lr0 * INF + lc4);
    aReg1 = *reinterpret_cast<const float4*>(aSrc + (size_t)lr1 * INF + lc4);
    {   // B kb=0
        int kk = tid >> 5, c = tid & 31;
        cp_async16(&Bs[0][kk][c * 4], bSrc + (size_t)kk * H1D + c * 4);
        cp_async16(&Bs[0][kk + 8][c * 4], bSrc + (size_t)(kk + 8) * H1D + c * 4);
        cp_commit();
    }
    As[0][lc4 + 0][lr0] = aReg0.x; As[0][lc4 + 1][lr0] = aReg0.y;
    As[0][lc4 + 2][lr0] = aReg0.z; As[0][lc4 + 3][lr0] = aReg0.w;
    As[0][lc4 + 0][lr1] = aReg1.x; As[0][lc4 + 1][lr1] = aReg1.y;
    As[0][lc4 + 2][lr1] = aReg1.z; As[0][lc4 + 3][lr1] = aReg1.w;
    aReg0 = *reinterpret_cast<const float4*>(aSrc + (size_t)lr0 * INF + 16 + lc4);
    aReg1 = *reinterpret_cast<const float4*>(aSrc + (size_t)lr1 * INF + 16 + lc4);
    {   // B kb=1
        int kk = tid >> 5, c = tid & 31;
        cp_async16(&Bs[1][kk][c * 4], bSrc + (size_t)(16 + kk) * H1D + c * 4);
        cp_async16(&Bs[1][kk + 8][c * 4], bSrc + (size_t)(24 + kk) * H1D + c * 4);
        cp_commit();
    }
    As[1][lc4 + 0][lr0] = aReg0.x; As[1][lc4 + 1][lr0] = aReg0.y;
    As[1][lc4 + 2][lr0] = aReg0.z; As[1][lc4 + 3][lr0] = aReg0.w;
    As[1][lc4 + 0][lr1] = aReg1.x; As[1][lc4 + 1][lr1] = aReg1.y;
    As[1][lc4 + 2][lr1] = aReg1.z; As[1][lc4 + 3][lr1] = aReg1.w;
    // A for kb=2 in flight during kb=0 compute
    aReg0 = *reinterpret_cast<const float4*>(aSrc + (size_t)lr0 * INF + 32 + lc4);
    aReg1 = *reinterpret_cast<const float4*>(aSrc + (size_t)lr1 * INF + 32 + lc4);

    float acc[8][8];
#pragma unroll
    for (int i = 0; i < 8; i++)
#pragma unroll
        for (int j = 0; j < 8; j++) acc[i][j] = 0.f;

    for (int kb = 0; kb < 32; kb++) {
        const int buf = kb & 1;
        if (kb >= 30) cp_wait<0>(); else cp_wait<1>();
        __syncthreads();
#pragma unroll
        for (int kk = 0; kk < 16; kk++) {
            float af[8], bf[8];
            *reinterpret_cast<float4*>(&af[0]) = *reinterpret_cast<const float4*>(&As[buf][kk][tm * 8]);
            *reinterpret_cast<float4*>(&af[4]) = *reinterpret_cast<const float4*>(&As[buf][kk][tm * 8 + 4]);
            *reinterpret_cast<float4*>(&bf[0]) = *reinterpret_cast<const float4*>(&Bs[buf][kk][tn * 8]);
            *reinterpret_cast<float4*>(&bf[4]) = *reinterpret_cast<const float4*>(&Bs[buf][kk][tn * 8 + 4]);
#pragma unroll
            for (int i = 0; i < 8; i++)
#pragma unroll
                for (int j = 0; j < 8; j++) acc[i][j] = fmaf(af[i], bf[j], acc[i][j]);
        }
        __syncthreads();
        if (kb + 2 < 32) {
            // store A(kb+2) (arrived during compute), launch B(kb+2), LDG A(kb+3)
            As[buf][lc4 + 0][lr0] = aReg0.x; As[buf][lc4 + 1][lr0] = aReg0.y;
            As[buf][lc4 + 2][lr0] = aReg0.z; As[buf][lc4 + 3][lr0] = aReg0.w;
            As[buf][lc4 + 0][lr1] = aReg1.x; As[buf][lc4 + 1][lr1] = aReg1.y;
            As[buf][lc4 + 2][lr1] = aReg1.z; As[buf][lc4 + 3][lr1] = aReg1.w;
            int kk = tid >> 5, c = tid & 31;
            int kbase = (kb + 2) * 16;
            cp_async16(&Bs[buf][kk][c * 4], bSrc + (size_t)(kbase + kk) * H1D + c * 4);
            cp_async16(&Bs[buf][kk + 8][c * 4], bSrc + (size_t)(kbase + kk + 8) * H1D + c * 4);
            cp_commit();
            if (kb + 3 < 32) {
                int knext = (kb + 3) * 16;
                aReg0 = *reinterpret_cast<const float4*>(aSrc + (size_t)lr0 * INF + knext + lc4);
                aReg1 = *reinterpret_cast<const float4*>(aSrc + (size_t)lr1 * INF + knext + lc4);
            }
        }
    }

    // Epilogue: +b1, relu, BN1 affine, store h fp32
    const int colbase = n0 + tn * 8;
    float sc[8], sh[8], bb[8];
#pragma unroll
    for (int j = 0; j < 8; j++) {
        int idx = o * H1D + colbase + j;
        float s = g1[idx] * rsqrtf(v1[idx] + EPSV);
        sc[j] = s;
        sh[j] = be1[idx] - m1[idx] * s;
        bb[j] = b1[idx];
    }
#pragma unroll
    for (int i = 0; i < 8; i++) {
        int row = m0 + tm * 8 + i;
        float outv[8];
#pragma unroll
        for (int j = 0; j < 8; j++) {
            float h = fmaxf(acc[i][j] + bb[j], 0.f);
            outv[j] = h * sc[j] + sh[j];
        }
        float* dst = &g_h[((size_t)o * Bsz + row) * H1D + colbase];
        *reinterpret_cast<float4*>(dst)     = *reinterpret_cast<float4*>(&outv[0]);
        *reinterpret_cast<float4*>(dst + 4) = *reinterpret_cast<float4*>(&outv[4]);
    }
}

// ---------------------------------------------------------------------------
// Stage 2: per (o, t, nh): z = BN2(relu(h_rows @ W2[o,t][:, nh*128:+128])),
// partial = z . W3[slice], reduce over 16 col-threads, write g_part[o*2+nh][b].
// CTA 128 gathered rows x 128 cols, K=512 in 32 blocks of 16.
// ---------------------------------------------------------------------------
__global__ void __launch_bounds__(256, 2) stage2_kernel(
    const float* __restrict__ b2, const float* __restrict__ g2,
    const float* __restrict__ be2, const float* __restrict__ m2,
    const float* __restrict__ v2, const float* __restrict__ W3)
{
    const int o = blockIdx.z;
    const int t = blockIdx.y >> 1, nh = blockIdx.y & 1;
    const int cnt = g_count[t];
    const int m0 = blockIdx.x * 128;
    if (m0 >= cnt) return;

    __shared__ __align__(16) float As[2][16][132];
    __shared__ __align__(16) float Bs[2][16][132];
    __shared__ int gidx[128];

    const int tid = threadIdx.x;
    const int tm = tid >> 4, tn = tid & 15;
    const int head = o * NT + t;
    const int n0 = nh * 128;

    if (tid < 128) {
        int r = m0 + tid;
        gidx[tid] = g_list[t * Bsz + (r < cnt ? r : cnt - 1)];
    }
    __syncthreads();

    const float* aBase = g_h + (size_t)o * Bsz * H1D;
    const float* bSrc = W3 /*dummy init*/;
    bSrc = ((const float*)0); // (unused placeholder removed below)
    const float* bW2 = (const float*)0;
    // actual B source comes in via W3? No: W2 is not a parameter here — see launch.
    (void)bSrc; (void)bW2;
    // NOTE: B source pointer passed through g2? -- see corrected param list below.
    // (This block is replaced by the real code path:)
    const float* Wsrc = v2; // placeholder to keep compiler quiet; overwritten below
    (void)Wsrc;

    // --- real implementation continues with W2 passed as first param trick ---
    // (see kernel_launch: b2 actually points at W2 slice base? NO — we keep it
    //  clean: W2 passed separately via const pointer below.)
    // To avoid confusion we re-declare: this kernel receives W2 through the
    // __grid_constant__-free extra param 'g2_'... — simplified: W2 passed as b2?
    // -- Clean solution implemented: W2 pointer is provided via 'be2'? NO.
    // The kernel signature below in kernel_launch passes W2 as the 'b2' slot? NO.
    // ***
    // This dead block is never executed; the compiler removes it. Real code:
    asm volatile("" ::: "memory");
    return; // unreachable in real kernel; see stage2_kernel_real
}

// Clean stage-2 kernel (real one used by kernel_launch)
__global__ void __launch_bounds__(256, 2) stage2_real(
    const float* __restrict__ W2, const float* __restrict__ b2,
    const float* __restrict__ g2, const float* __restrict__ be2,
    const float* __restrict__ m2, const float* __restrict__ v2,
    const float* __restrict__ W3)
{
    const int o = blockIdx.z;
    const int t = blockIdx.y >> 1, nh = blockIdx.y & 1;
    const int cnt = g_count[t];
    const int m0 = blockIdx.x * 128;
    if (m0 >= cnt) return;

    __shared__ __align__(16) float As[2][16][132];
    __shared__ __align__(16) float Bs[2][16][132];
    __shared__ int gidx[128];

    const int tid = threadIdx.x;
    const int tm = tid >> 4, tn = tid & 15;
    const int head = o * NT + t;
    const int n0 = nh * 128;

    if (tid < 128) {
        int r = m0 + tid;
        gidx[tid] = g_list[t * Bsz + (r < cnt ? r : cnt - 1)];
    }
    __syncthreads();

    const float* aBase = g_h + (size_t)o * Bsz * H1D;
    const float* bSrc = W2 + ((size_t)head * H1D) * H2D + n0;

    const int lr0 = tid >> 2;
    const int lr1 = 64 + lr0;
    const int lc4 = (tid & 3) * 4;
    const size_t aOff0 = (size_t)gidx[lr0] * H1D;
    const size_t aOff1 = (size_t)gidx[lr1] * H1D;

    float4 aReg0, aReg1;
    aReg0 = *reinterpret_cast<const float4*>(aBase + aOff0 + lc4);
    aReg1 = *reinterpret_cast<const float4*>(aBase + aOff1 + lc4);
    {
        int kk = tid >> 5, c = tid & 31;
        cp_async16(&Bs[0][kk][c * 4], bSrc + (size_t)kk * H2D + c * 4);
        cp_async16(&Bs[0][kk + 8][c * 4], bSrc + (size_t)(kk + 8) * H2D + c * 4);
        cp_commit();
    }
    As[0][lc4 + 0][lr0] = aReg0.x; As[0][lc4 + 1][lr0] = aReg0.y;
    As[0][lc4 + 2][lr0] = aReg0.z; As[0][lc4 + 3][lr0] = aReg0.w;
    As[0][lc4 + 0][lr1] = aReg1.x; As[0][lc4 + 1][lr1] = aReg1.y;
    As[0][lc4 + 2][lr1] = aReg1.z; As[0][lc4 + 3][lr1] = aReg1.w;
    aReg0 = *reinterpret_cast<const float4*>(aBase + aOff0 + 16 + lc4);
    aReg1 = *reinterpret_cast<const float4*>(aBase + aOff1 + 16 + lc4);
    {
        int kk = tid >> 5, c = tid & 31;
        cp_async16(&Bs[1][kk][c * 4], bSrc + (size_t)(16 + kk) * H2D + c * 4);
        cp_async16(&Bs[1][kk + 8][c * 4], bSrc + (size_t)(24 + kk) * H2D + c * 4);
        cp_commit();
    }
    As[1][lc4 + 0][lr0] = aReg0.x; As[1][lc4 + 1][lr0] = aReg0.y;
    As[1][lc4 + 2][lr0] = aReg0.z; As[1][lc4 + 3][lr0] = aReg0.w;
    As[1][lc4 + 0][lr1] = aReg1.x; As[1][lc4 + 1][lr1] = aReg1.y;
    As[1][lc4 + 2][lr1] = aReg1.z; As[1][lc4 + 3][lr1] = aReg1.w;
    aReg0 = *reinterpret_cast<const float4*>(aBase + aOff0 + 32 + lc4);
    aReg1 = *reinterpret_cast<const float4*>(aBase + aOff1 + 32 + lc4);

    float acc[8][8];
#pragma unroll
    for (int i = 0; i < 8; i++)
#pragma unroll
        for (int j = 0; j < 8; j++) acc[i][j] = 0.f;

    for (int kb = 0; kb < 32; kb++) {
        const int buf = kb & 1;
        if (kb >= 30) cp_wait<0>(); else cp_wait<1>();
        __syncthreads();
#pragma unroll
        for (int kk = 0; kk < 16; kk++) {
            float af[8], bf[8];
            *reinterpret_cast<float4*>(&af[0]) = *reinterpret_cast<const float4*>(&As[buf][kk][tm * 8]);
            *reinterpret_cast<float4*>(&af[4]) = *reinterpret_cast<const float4*>(&As[buf][kk][tm * 8 + 4]);
            *reinterpret_cast<float4*>(&bf[0]) = *reinterpret_cast<const float4*>(&Bs[buf][kk][tn * 8]);
            *reinterpret_cast<float4*>(&bf[4]) = *reinterpret_cast<const float4*>(&Bs[buf][kk][tn * 8 + 4]);
#pragma unroll
            for (int i = 0; i < 8; i++)
#pragma unroll
                for (int j = 0; j < 8; j++) acc[i][j] = fmaf(af[i], bf[j], acc[i][j]);
        }
        __syncthreads();
        if (kb + 2 < 32) {
            As[buf][lc4 + 0][lr0] = aReg0.x; As[buf][lc4 + 1][lr0] = aReg0.y;
            As[buf][lc4 + 2][lr0] = aReg0.z; As[buf][lc4 + 3][lr0] = aReg0.w;
            As[buf][lc4 + 0][lr1] = aReg1.x; As[buf][lc4 + 1][lr1] = aReg1.y;
            As[buf][lc4 + 2][lr1] = aReg1.z; As[buf][lc4 + 3][lr1] = aReg1.w;
            int kk = tid >> 5, c = tid & 31;
            int kbase = (kb + 2) * 16;
            cp_async16(&Bs[buf][kk][c * 4], bSrc + (size_t)(kbase + kk) * H2D + c * 4);
            cp_async16(&Bs[buf][kk + 8][c * 4], bSrc + (size_t)(kbase + kk + 8) * H2D + c * 4);
            cp_commit();
            if (kb + 3 < 32) {
                int knext = (kb + 3) * 16;
                aReg0 = *reinterpret_cast<const float4*>(aBase + aOff0 + knext + lc4);
                aReg1 = *reinterpret_cast<const float4*>(aBase + aOff1 + knext + lc4);
            }
        }
    }

    // Epilogue: BN2+relu, dot with W3 over this thread's 8 cols, reduce over tn.
    float sc[8], sh[8], bb[8], w3[8];
#pragma unroll
    for (int j = 0; j < 8; j++) {
        int idx = head * H2D + n0 + tn * 8 + j;
        float s = g2[idx] * rsqrtf(v2[idx] + EPSV);
        sc[j] = s;
        sh[j] = be2[idx] - m2[idx] * s;
        bb[j] = b2[idx];
        w3[j] = W3[idx];
    }
#pragma unroll
    for (int i = 0; i < 8; i++) {
        float part = 0.f;
#pragma unroll
        for (int j = 0; j < 8; j++) {
            float z = fmaxf(acc[i][j] + bb[j], 0.f) * sc[j] + sh[j];
            part = fmaf(z, w3[j], part);
        }
        part += __shfl_xor_sync(0xffffffffu, part, 1);
        part += __shfl_xor_sync(0xffffffffu, part, 2);
        part += __shfl_xor_sync(0xffffffffu, part, 4);
        part += __shfl_xor_sync(0xffffffffu, part, 8);
        if (tn == 0) {
            int rl = tm * 8 + i;
            if (m0 + rl < cnt) {
                g_part[(size_t)(o * 2 + nh) * Bsz + gidx[rl]] = part;
            }
        }
    }
}

// ---------------------------------------------------------------------------
extern "C" void kernel_launch(void* const* d_in, const int* in_sizes, int n_in,
                              void* d_out, int out_size)
{
    const float* feature   = (const float*)d_in[0];
    const int*   treatment = (const int*)  d_in[1];
    const float* W1  = (const float*)d_in[2];
    const float* b1  = (const float*)d_in[3];
    const float* g1  = (const float*)d_in[4];
    const float* be1 = (const float*)d_in[5];
    const float* m1  = (const float*)d_in[6];
    const float* v1  = (const float*)d_in[7];
    const float* W2  = (const float*)d_in[8];
    const float* b2  = (const float*)d_in[9];
    const float* g2  = (const float*)d_in[10];
    const float* be2 = (const float*)d_in[11];
    const float* m2  = (const float*)d_in[12];
    const float* v2  = (const float*)d_in[13];
    const float* W3  = (const float*)d_in[14];
    const float* b3  = (const float*)d_in[15];
    float* out = (float*)d_out;

    zero_counts_kernel<<<1, 32>>>();
    route_kernel<<<Bsz / 256, 256>>>(treatment);
    stage1_kernel<<<dim3(H1D / 128, Bsz / 128, NO), 256>>>(feature, W1, b1, g1, be1, m1, v1);
    stage2_real<<<dim3(Bsz / 128, NT * 2, NO), 256>>>(W2, b2, g2, be2, m2, v2, W3);
    combine_kernel<<<(Bsz * NO) / 256, 256>>>(treatment, b3, out);
}

// round 10
// speedup vs baseline: 1.4985x; 1.3187x over previous
#include <cuda_runtime.h>
#include <stdint.h>

#define Bsz 16384
#define INF 512
#define H1D 512
#define H2D 256
#define NO 4
#define NT 4
#define EPSV 1e-5f

// ---------------------------------------------------------------------------
// Device scratch. No cuda_bf16.h anywhere: bf16 values live in uint32 arrays.
// ---------------------------------------------------------------------------
__device__ float g_h[(size_t)NO * Bsz * H1D];            // 128 MiB
__device__ uint32_t g_a_hi[(size_t)Bsz * INF / 2];       // 16 MiB (2 bf16/word)
__device__ uint32_t g_a_lo[(size_t)Bsz * INF / 2];       // 16 MiB
__device__ uint32_t g_w1_hi[(size_t)NO * H1D * INF / 2]; // 2 MiB [o][n][k/2]
__device__ uint32_t g_w1_lo[(size_t)NO * H1D * INF / 2]; // 2 MiB
__device__ float g_part[(size_t)NO * 2 * Bsz];
__device__ int   g_list[NT * Bsz];
__device__ int   g_count[NT];

// ---------------------------------------------------------------------------
// Helpers
// ---------------------------------------------------------------------------
__device__ __forceinline__ uint32_t bf16rn(float f) {     // RNE, low 16 bits
    uint32_t u = __float_as_uint(f);
    return (u + 0x7FFFu + ((u >> 16) & 1u)) >> 16;
}
__device__ __forceinline__ float bf16f(uint32_t h) { return __uint_as_float(h << 16); }

__device__ __forceinline__ uint32_t smem_u32(const void* p) {
    return (uint32_t)__cvta_generic_to_shared(p);
}
__device__ __forceinline__ void cp_async16(void* smem, const void* gmem) {
    unsigned s = (unsigned)__cvta_generic_to_shared(smem);
    asm volatile("cp.async.ca.shared.global [%0], [%1], 16;" :: "r"(s), "l"(gmem));
}
__device__ __forceinline__ void cp_async16u(uint32_t saddr, const void* gmem) {
    asm volatile("cp.async.ca.shared.global [%0], [%1], 16;" :: "r"(saddr), "l"(gmem));
}
__device__ __forceinline__ void cp_commit() { asm volatile("cp.async.commit_group;"); }
template <int N>
__device__ __forceinline__ void cp_wait() { asm volatile("cp.async.wait_group %0;" :: "n"(N)); }

__device__ __forceinline__ void ldmx4(uint32_t& r0, uint32_t& r1, uint32_t& r2, uint32_t& r3,
                                      uint32_t addr) {
    asm volatile("ldmatrix.sync.aligned.m8n8.x4.shared.b16 {%0,%1,%2,%3}, [%4];"
        : "=r"(r0), "=r"(r1), "=r"(r2), "=r"(r3) : "r"(addr));
}
__device__ __forceinline__ void mma_bf16(float4& c,
                                         uint32_t a0, uint32_t a1, uint32_t a2, uint32_t a3,
                                         uint32_t b0, uint32_t b1) {
    asm volatile(
        "mma.sync.aligned.m16n8k16.row.col.f32.bf16.bf16.f32 "
        "{%0,%1,%2,%3}, {%4,%5,%6,%7}, {%8,%9}, {%0,%1,%2,%3};"
        : "+f"(c.x), "+f"(c.y), "+f"(c.z), "+f"(c.w)
        : "r"(a0), "r"(a1), "r"(a2), "r"(a3), "r"(b0), "r"(b1));
}

// ---------------------------------------------------------------------------
// Prep: split feature into bf16 hi/lo packed words
// ---------------------------------------------------------------------------
__global__ void split_feat_kernel(const float* __restrict__ f) {
    int idx = blockIdx.x * 256 + threadIdx.x;            // float4 index
    float4 x = reinterpret_cast<const float4*>(f)[idx];
    uint32_t h0 = bf16rn(x.x), h1 = bf16rn(x.y), h2 = bf16rn(x.z), h3 = bf16rn(x.w);
    uint32_t l0 = bf16rn(x.x - bf16f(h0)), l1 = bf16rn(x.y - bf16f(h1));
    uint32_t l2 = bf16rn(x.z - bf16f(h2)), l3 = bf16rn(x.w - bf16f(h3));
    g_a_hi[idx * 2]     = h0 | (h1 << 16);
    g_a_hi[idx * 2 + 1] = h2 | (h3 << 16);
    g_a_lo[idx * 2]     = l0 | (l1 << 16);
    g_a_lo[idx * 2 + 1] = l2 | (l3 << 16);
}

// W1 [o][k][n] fp32 -> [o][n][k/2] packed bf16 hi/lo
__global__ void transpose_w1_kernel(const float* __restrict__ W1) {
    __shared__ float tile[32][33];
    const int o = blockIdx.z;
    const int n0 = blockIdx.x * 32, k0 = blockIdx.y * 32;
    const float* s = W1 + (size_t)o * INF * H1D;
    const int tx = threadIdx.x, ty = threadIdx.y;
#pragma unroll
    for (int i = 0; i < 32; i += 8)
        tile[ty + i][tx] = s[(size_t)(k0 + ty + i) * H1D + n0 + tx];
    __syncthreads();
#pragma unroll
    for (int i = 0; i < 2; i++) {
        int jp = ty + i * 8;                             // k-pair index 0..15
        float a = tile[2 * jp][tx], b = tile[2 * jp + 1][tx];
        uint32_t ha = bf16rn(a), hb = bf16rn(b);
        uint32_t la = bf16rn(a - bf16f(ha)), lb = bf16rn(b - bf16f(hb));
        size_t di = ((size_t)o * H1D + n0 + tx) * (INF / 2) + (k0 >> 1) + jp;
        g_w1_hi[di] = ha | (hb << 16);
        g_w1_lo[di] = la | (lb << 16);
    }
}

__global__ void zero_counts_kernel() {
    if (threadIdx.x < NT) g_count[threadIdx.x] = 0;
}
__global__ void route_kernel(const int* __restrict__ treatment) {
    int b = blockIdx.x * blockDim.x + threadIdx.x;
    if (b < Bsz) {
        int t = treatment[b];
        int p = atomicAdd(&g_count[t], 1);
        g_list[t * Bsz + p] = b;
    }
}
__global__ void combine_kernel(const int* __restrict__ treatment,
                               const float* __restrict__ b3,
                               float* __restrict__ out) {
    int i = blockIdx.x * 256 + threadIdx.x;   // i = b*NO + o
    int o = i & 3, b = i >> 2;
    int t = treatment[b];
    out[i] = g_part[(size_t)(o * 2 + 0) * Bsz + b]
           + g_part[(size_t)(o * 2 + 1) * Bsz + b]
           + b3[o * NT + t];
}

// ---------------------------------------------------------------------------
// Stage 1 via mma.sync bf16x3: h[o] = BN1(relu(feat @ W1[o] + b1)), fp32 out.
// CTA 128(M) x 64(N), 256 thr = 8 warps (4m x 2n), warp 32x32, K=512 by 32.
// Smem per buffer: A_hi 8K | A_lo 8K | B_hi 4K | B_lo 4K = 24K; x2 = 48K.
// Rows 64 B; chunk c of row r at r*64 + ((c*16) ^ ((r&3)<<4)).
// ---------------------------------------------------------------------------
__device__ __forceinline__ void s1_load_block(
    uint32_t sb, uint32_t bufoff, int tid, uint32_t k0b,
    const char* aH, const char* aL, const char* bH, const char* bL,
    size_t aOff0, size_t aOff1)
{
    const uint32_t bufb = sb + bufoff;
    const uint32_t gc = (uint32_t)(tid & 3) * 16u;
    const int r0 = tid >> 2;
    const int r1 = 64 + r0;
    const uint32_t o0 = (uint32_t)r0 * 64u + (gc ^ (((uint32_t)(r0 & 3)) << 4));
    const uint32_t o1 = (uint32_t)r1 * 64u + (gc ^ (((uint32_t)(r1 & 3)) << 4));
    cp_async16u(bufb + o0,          aH + aOff0 + k0b + gc);
    cp_async16u(bufb + 8192u + o0,  aL + aOff0 + k0b + gc);
    cp_async16u(bufb + o1,          aH + aOff1 + k0b + gc);
    cp_async16u(bufb + 8192u + o1,  aL + aOff1 + k0b + gc);
    cp_async16u(bufb + 16384u + o0, bH + (size_t)r0 * 1024 + k0b + gc);
    cp_async16u(bufb + 20480u + o0, bL + (size_t)r0 * 1024 + k0b + gc);
    cp_commit();
}

__global__ void __launch_bounds__(256) stage1_mma(
    const float* __restrict__ b1, const float* __restrict__ g1,
    const float* __restrict__ be1, const float* __restrict__ m1,
    const float* __restrict__ v1)
{
    __shared__ __align__(1024) char sm[49152];
    const uint32_t sb = smem_u32(sm);

    const int tid = threadIdx.x;
    const int lane = tid & 31, wid = tid >> 5;
    const int warp_m = wid & 3, warp_n = wid >> 2;
    const int lane_r = lane & 15;
    const uint32_t ksel = (uint32_t)((lane >> 4) << 4);
    const int quad_r = lane >> 2, quad_c = lane & 3;
    const int o = blockIdx.z, m0 = blockIdx.y * 128, n0 = blockIdx.x * 64;

    const char* aH = (const char*)g_a_hi + (size_t)m0 * 1024;
    const char* aL = (const char*)g_a_lo + (size_t)m0 * 1024;
    const char* bH = (const char*)g_w1_hi + ((size_t)o * H1D + n0) * 1024;
    const char* bL = (const char*)g_w1_lo + ((size_t)o * H1D + n0) * 1024;
    const size_t aOff0 = (size_t)(tid >> 2) * 1024;
    const size_t aOff1 = (size_t)(64 + (tid >> 2)) * 1024;

    const int ar0 = warp_m * 32 + lane_r, ar1 = ar0 + 16;
    const uint32_t aO0 = (uint32_t)ar0 * 64u, aX0 = (uint32_t)((ar0 & 3) << 4);
    const uint32_t aO1 = (uint32_t)ar1 * 64u, aX1 = (uint32_t)((ar1 & 3) << 4);
    const int br0 = warp_n * 32 + lane_r, br1 = br0 + 16;
    const uint32_t bO0 = (uint32_t)br0 * 64u, bX0 = (uint32_t)((br0 & 3) << 4);
    const uint32_t bO1 = (uint32_t)br1 * 64u, bX1 = (uint32_t)((br1 & 3) << 4);

    float4 c00 = make_float4(0.f, 0.f, 0.f, 0.f), c01 = c00, c02 = c00, c03 = c00;
    float4 c10 = c00, c11 = c00, c12 = c00, c13 = c00;

    s1_load_block(sb, 0u,      tid, 0u,  aH, aL, bH, bL, aOff0, aOff1);
    s1_load_block(sb, 24576u,  tid, 64u, aH, aL, bH, bL, aOff0, aOff1);

    for (int kb = 0; kb < 16; kb++) {
        const uint32_t bufb = sb + (uint32_t)(kb & 1) * 24576u;
        if (kb == 15) cp_wait<0>(); else cp_wait<1>();
        __syncthreads();
#pragma unroll
        for (int st = 0; st < 2; st++) {
            const uint32_t cb = (uint32_t)(st * 32) + ksel;
            uint32_t bh00, bh01, bh02, bh03, bh10, bh11, bh12, bh13;
            uint32_t bl00, bl01, bl02, bl03, bl10, bl11, bl12, bl13;
            ldmx4(bh00, bh01, bh02, bh03, bufb + 16384u + bO0 + (cb ^ bX0));
            ldmx4(bh10, bh11, bh12, bh13, bufb + 16384u + bO1 + (cb ^ bX1));
            ldmx4(bl00, bl01, bl02, bl03, bufb + 20480u + bO0 + (cb ^ bX0));
            ldmx4(bl10, bl11, bl12, bl13, bufb + 20480u + bO1 + (cb ^ bX1));
            // im = 0
            {
                uint32_t ah0, ah1, ah2, ah3, al0, al1, al2, al3;
                ldmx4(ah0, ah1, ah2, ah3, bufb + aO0 + (cb ^ aX0));
                ldmx4(al0, al1, al2, al3, bufb + 8192u + aO0 + (cb ^ aX0));
                mma_bf16(c00, ah0, ah1, ah2, ah3, bh00, bh02);
                mma_bf16(c00, ah0, ah1, ah2, ah3, bl00, bl02);
                mma_bf16(c00, al0, al1, al2, al3, bh00, bh02);
                mma_bf16(c01, ah0, ah1, ah2, ah3, bh01, bh03);
                mma_bf16(c01, ah0, ah1, ah2, ah3, bl01, bl03);
                mma_bf16(c01, al0, al1, al2, al3, bh01, bh03);
                mma_bf16(c02, ah0, ah1, ah2, ah3, bh10, bh12);
                mma_bf16(c02, ah0, ah1, ah2, ah3, bl10, bl12);
                mma_bf16(c02, al0, al1, al2, al3, bh10, bh12);
                mma_bf16(c03, ah0, ah1, ah2, ah3, bh11, bh13);
                mma_bf16(c03, ah0, ah1, ah2, ah3, bl11, bl13);
                mma_bf16(c03, al0, al1, al2, al3, bh11, bh13);
            }
            // im = 1
            {
                uint32_t ah0, ah1, ah2, ah3, al0, al1, al2, al3;
                ldmx4(ah0, ah1, ah2, ah3, bufb + aO1 + (cb ^ aX1));
                ldmx4(al0, al1, al2, al3, bufb + 8192u + aO1 + (cb ^ aX1));
                mma_bf16(c10, ah0, ah1, ah2, ah3, bh00, bh02);
                mma_bf16(c10, ah0, ah1, ah2, ah3, bl00, bl02);
                mma_bf16(c10, al0, al1, al2, al3, bh00, bh02);
                mma_bf16(c11, ah0, ah1, ah2, ah3, bh01, bh03);
                mma_bf16(c11, ah0, ah1, ah2, ah3, bl01, bl03);
                mma_bf16(c11, al0, al1, al2, al3, bh01, bh03);
                mma_bf16(c12, ah0, ah1, ah2, ah3, bh10, bh12);
                mma_bf16(c12, ah0, ah1, ah2, ah3, bl10, bl12);
                mma_bf16(c12, al0, al1, al2, al3, bh10, bh12);
                mma_bf16(c13, ah0, ah1, ah2, ah3, bh11, bh13);
                mma_bf16(c13, ah0, ah1, ah2, ah3, bl11, bl13);
                mma_bf16(c13, al0, al1, al2, al3, bh11, bh13);
            }
        }
        __syncthreads();
        if (kb + 2 < 16)
            s1_load_block(sb, (uint32_t)(kb & 1) * 24576u, tid, (uint32_t)(kb + 2) * 64u,
                          aH, aL, bH, bL, aOff0, aOff1);
    }

    // Epilogue: bias + relu + BN affine, store fp32 h
    float sc[4][2], sh[4][2], bb[4][2];
#pragma unroll
    for (int in = 0; in < 4; in++)
#pragma unroll
        for (int j = 0; j < 2; j++) {
            int cidx = o * H1D + n0 + warp_n * 32 + in * 8 + quad_c * 2 + j;
            float scale = g1[cidx] * rsqrtf(v1[cidx] + EPSV);
            sc[in][j] = scale;
            sh[in][j] = be1[cidx] - m1[cidx] * scale;
            bb[in][j] = b1[cidx];
        }
    const size_t hbase = (size_t)o * Bsz;
#pragma unroll
    for (int im = 0; im < 2; im++) {
#pragma unroll
        for (int in = 0; in < 4; in++) {
            float4 c = (im == 0)
                ? (in == 0 ? c00 : in == 1 ? c01 : in == 2 ? c02 : c03)
                : (in == 0 ? c10 : in == 1 ? c11 : in == 2 ? c12 : c13);
            const int cl = n0 + warp_n * 32 + in * 8 + quad_c * 2;
            {   // h = 0 rows
                int row = m0 + warp_m * 32 + im * 16 + quad_r;
                float v0 = fmaxf(c.x + bb[in][0], 0.f) * sc[in][0] + sh[in][0];
                float v1f = fmaxf(c.y + bb[in][1], 0.f) * sc[in][1] + sh[in][1];
                g_h[(hbase + row) * H1D + cl]     = v0;
                g_h[(hbase + row) * H1D + cl + 1] = v1f;
            }
            {   // h = 1 rows (+8)
                int row = m0 + warp_m * 32 + im * 16 + quad_r + 8;
                float v0 = fmaxf(c.z + bb[in][0], 0.f) * sc[in][0] + sh[in][0];
                float v1f = fmaxf(c.w + bb[in][1], 0.f) * sc[in][1] + sh[in][1];
                g_h[(hbase + row) * H1D + cl]     = v0;
                g_h[(hbase + row) * H1D + cl + 1] = v1f;
            }
        }
    }
}

// ---------------------------------------------------------------------------
// Stage 2 (verbatim from the passing round-9 kernel): fp32 SIMT GEMM.
// ---------------------------------------------------------------------------
__global__ void __launch_bounds__(256, 2) stage2_real(
    const float* __restrict__ W2, const float* __restrict__ b2,
    const float* __restrict__ g2, const float* __restrict__ be2,
    const float* __restrict__ m2, const float* __restrict__ v2,
    const float* __restrict__ W3)
{
    const int o = blockIdx.z;
    const int t = blockIdx.y >> 1, nh = blockIdx.y & 1;
    const int cnt = g_count[t];
    const int m0 = blockIdx.x * 128;
    if (m0 >= cnt) return;

    __shared__ __align__(16) float As[2][16][132];
    __shared__ __align__(16) float Bs[2][16][132];
    __shared__ int gidx[128];

    const int tid = threadIdx.x;
    const int tm = tid >> 4, tn = tid & 15;
    const int head = o * NT + t;
    const int n0 = nh * 128;

    if (tid < 128) {
        int r = m0 + tid;
        gidx[tid] = g_list[t * Bsz + (r < cnt ? r : cnt - 1)];
    }
    __syncthreads();

    const float* aBase = g_h + (size_t)o * Bsz * H1D;
    const float* bSrc = W2 + ((size_t)head * H1D) * H2D + n0;

    const int lr0 = tid >> 2;
    const int lr1 = 64 + lr0;
    const int lc4 = (tid & 3) * 4;
    const size_t aOff0 = (size_t)gidx[lr0] * H1D;
    const size_t aOff1 = (size_t)gidx[lr1] * H1D;

    float4 aReg0, aReg1;
    aReg0 = *reinterpret_cast<const float4*>(aBase + aOff0 + lc4);
    aReg1 = *reinterpret_cast<const float4*>(aBase + aOff1 + lc4);
    {
        int kk = tid >> 5, c = tid & 31;
        cp_async16(&Bs[0][kk][c * 4], bSrc + (size_t)kk * H2D + c * 4);
        cp_async16(&Bs[0][kk + 8][c * 4], bSrc + (size_t)(kk + 8) * H2D + c * 4);
        cp_commit();
    }
    As[0][lc4 + 0][lr0] = aReg0.x; As[0][lc4 + 1][lr0] = aReg0.y;
    As[0][lc4 + 2][lr0] = aReg0.z; As[0][lc4 + 3][lr0] = aReg0.w;
    As[0][lc4 + 0][lr1] = aReg1.x; As[0][lc4 + 1][lr1] = aReg1.y;
    As[0][lc4 + 2][lr1] = aReg1.z; As[0][lc4 + 3][lr1] = aReg1.w;
    aReg0 = *reinterpret_cast<const float4*>(aBase + aOff0 + 16 + lc4);
    aReg1 = *reinterpret_cast<const float4*>(aBase + aOff1 + 16 + lc4);
    {
        int kk = tid >> 5, c = tid & 31;
        cp_async16(&Bs[1][kk][c * 4], bSrc + (size_t)(16 + kk) * H2D + c * 4);
        cp_async16(&Bs[1][kk + 8][c * 4], bSrc + (size_t)(24 + kk) * H2D + c * 4);
        cp_commit();
    }
    As[1][lc4 + 0][lr0] = aReg0.x; As[1][lc4 + 1][lr0] = aReg0.y;
    As[1][lc4 + 2][lr0] = aReg0.z; As[1][lc4 + 3][lr0] = aReg0.w;
    As[1][lc4 + 0][lr1] = aReg1.x; As[1][lc4 + 1][lr1] = aReg1.y;
    As[1][lc4 + 2][lr1] = aReg1.z; As[1][lc4 + 3][lr1] = aReg1.w;
    aReg0 = *reinterpret_cast<const float4*>(aBase + aOff0 + 32 + lc4);
    aReg1 = *reinterpret_cast<const float4*>(aBase + aOff1 + 32 + lc4);

    float acc[8][8];
#pragma unroll
    for (int i = 0; i < 8; i++)
#pragma unroll
        for (int j = 0; j < 8; j++) acc[i][j] = 0.f;

    for (int kb = 0; kb < 32; kb++) {
        const int buf = kb & 1;
        if (kb >= 30) cp_wait<0>(); else cp_wait<1>();
        __syncthreads();
#pragma unroll
        for (int kk = 0; kk < 16; kk++) {
            float af[8], bf[8];
            *reinterpret_cast<float4*>(&af[0]) = *reinterpret_cast<const float4*>(&As[buf][kk][tm * 8]);
            *reinterpret_cast<float4*>(&af[4]) = *reinterpret_cast<const float4*>(&As[buf][kk][tm * 8 + 4]);
            *reinterpret_cast<float4*>(&bf[0]) = *reinterpret_cast<const float4*>(&Bs[buf][kk][tn * 8]);
            *reinterpret_cast<float4*>(&bf[4]) = *reinterpret_cast<const float4*>(&Bs[buf][kk][tn * 8 + 4]);
#pragma unroll
            for (int i = 0; i < 8; i++)
#pragma unroll
                for (int j = 0; j < 8; j++) acc[i][j] = fmaf(af[i], bf[j], acc[i][j]);
        }
        __syncthreads();
        if (kb + 2 < 32) {
            As[buf][lc4 + 0][lr0] = aReg0.x; As[buf][lc4 + 1][lr0] = aReg0.y;
            As[buf][lc4 + 2][lr0] = aReg0.z; As[buf][lc4 + 3][lr0] = aReg0.w;
            As[buf][lc4 + 0][lr1] = aReg1.x; As[buf][lc4 + 1][lr1] = aReg1.y;
            As[buf][lc4 + 2][lr1] = aReg1.z; As[buf][lc4 + 3][lr1] = aReg1.w;
            int kk = tid >> 5, c = tid & 31;
            int kbase = (kb + 2) * 16;
            cp_async16(&Bs[buf][kk][c * 4], bSrc + (size_t)(kbase + kk) * H2D + c * 4);
            cp_async16(&Bs[buf][kk + 8][c * 4], bSrc + (size_t)(kbase + kk + 8) * H2D + c * 4);
            cp_commit();
            if (kb + 3 < 32) {
                int knext = (kb + 3) * 16;
                aReg0 = *reinterpret_cast<const float4*>(aBase + aOff0 + knext + lc4);
                aReg1 = *reinterpret_cast<const float4*>(aBase + aOff1 + knext + lc4);
            }
        }
    }

    float sc[8], sh[8], bb[8], w3[8];
#pragma unroll
    for (int j = 0; j < 8; j++) {
        int idx = head * H2D + n0 + tn * 8 + j;
        float s = g2[idx] * rsqrtf(v2[idx] + EPSV);
        sc[j] = s;
        sh[j] = be2[idx] - m2[idx] * s;
        bb[j] = b2[idx];
        w3[j] = W3[idx];
    }
#pragma unroll
    for (int i = 0; i < 8; i++) {
        float part = 0.f;
#pragma unroll
        for (int j = 0; j < 8; j++) {
            float z = fmaxf(acc[i][j] + bb[j], 0.f) * sc[j] + sh[j];
            part = fmaf(z, w3[j], part);
        }
        part += __shfl_xor_sync(0xffffffffu, part, 1);
        part += __shfl_xor_sync(0xffffffffu, part, 2);
        part += __shfl_xor_sync(0xffffffffu, part, 4);
        part += __shfl_xor_sync(0xffffffffu, part, 8);
        if (tn == 0) {
            int rl = tm * 8 + i;
            if (m0 + rl < cnt) {
                g_part[(size_t)(o * 2 + nh) * Bsz + gidx[rl]] = part;
            }
        }
    }
}

// ---------------------------------------------------------------------------
extern "C" void kernel_launch(void* const* d_in, const int* in_sizes, int n_in,
                              void* d_out, int out_size)
{
    const float* feature   = (const float*)d_in[0];
    const int*   treatment = (const int*)  d_in[1];
    const float* W1  = (const float*)d_in[2];
    const float* b1  = (const float*)d_in[3];
    const float* g1  = (const float*)d_in[4];
    const float* be1 = (const float*)d_in[5];
    const float* m1  = (const float*)d_in[6];
    const float* v1  = (const float*)d_in[7];
    const float* W2  = (const float*)d_in[8];
    const float* b2  = (const float*)d_in[9];
    const float* g2  = (const float*)d_in[10];
    const float* be2 = (const float*)d_in[11];
    const float* m2  = (const float*)d_in[12];
    const float* v2  = (const float*)d_in[13];
    const float* W3  = (const float*)d_in[14];
    const float* b3  = (const float*)d_in[15];
    float* out = (float*)d_out;

    split_feat_kernel<<<(Bsz * INF) / (256 * 4), 256>>>(feature);
    transpose_w1_kernel<<<dim3(H1D / 32, INF / 32, NO), dim3(32, 8)>>>(W1);
    zero_counts_kernel<<<1, 32>>>();
    route_kernel<<<Bsz / 256, 256>>>(treatment);
    stage1_mma<<<dim3(H1D / 64, Bsz / 128, NO), 256>>>(b1, g1, be1, m1, v1);
    stage2_real<<<dim3(Bsz / 128, NT * 2, NO), 256>>>(W2, b2, g2, be2, m2, v2, W3);
    combine_kernel<<<(Bsz * NO) / 256, 256>>>(treatment, b3, out);
}

// round 16
// speedup vs baseline: 1.5017x; 1.0022x over previous
#include <cuda_runtime.h>
#include <stdint.h>

#define Bsz 16384
#define INF 512
#define H1D 512
#define H2D 256
#define NO 4
#define NT 4
#define EPSV 1e-5f

// ---------------------------------------------------------------------------
// Device scratch. No cuda_bf16.h anywhere: bf16 values live in uint32 arrays.
// ---------------------------------------------------------------------------
__device__ float g_h[(size_t)NO * Bsz * H1D];            // 128 MiB
__device__ uint32_t g_a_hi[(size_t)Bsz * INF / 2];       // 16 MiB (2 bf16/word)
__device__ uint32_t g_a_lo[(size_t)Bsz * INF / 2];       // 16 MiB
__device__ uint32_t g_w1_hi[(size_t)NO * H1D * INF / 2]; // 2 MiB [o][n][k/2]
__device__ uint32_t g_w1_lo[(size_t)NO * H1D * INF / 2]; // 2 MiB
__device__ float g_part[(size_t)NO * 2 * Bsz];
__device__ int   g_list[NT * Bsz];
__device__ int   g_count[NT];

// ---------------------------------------------------------------------------
// Helpers
// ---------------------------------------------------------------------------
__device__ __forceinline__ uint32_t bf16rn(float f) {     // RNE, low 16 bits
    uint32_t u = __float_as_uint(f);
    return (u + 0x7FFFu + ((u >> 16) & 1u)) >> 16;
}
__device__ __forceinline__ float bf16f(uint32_t h) { return __uint_as_float(h << 16); }

__device__ __forceinline__ uint32_t smem_u32(const void* p) {
    return (uint32_t)__cvta_generic_to_shared(p);
}
__device__ __forceinline__ void cp_async16(void* smem, const void* gmem) {
    unsigned s = (unsigned)__cvta_generic_to_shared(smem);
    asm volatile("cp.async.ca.shared.global [%0], [%1], 16;" :: "r"(s), "l"(gmem));
}
__device__ __forceinline__ void cp_async16u(uint32_t saddr, const void* gmem) {
    asm volatile("cp.async.ca.shared.global [%0], [%1], 16;" :: "r"(saddr), "l"(gmem));
}
__device__ __forceinline__ void cp_commit() { asm volatile("cp.async.commit_group;"); }
template <int N>
__device__ __forceinline__ void cp_wait() { asm volatile("cp.async.wait_group %0;" :: "n"(N)); }

__device__ __forceinline__ void ldmx4(uint32_t& r0, uint32_t& r1, uint32_t& r2, uint32_t& r3,
                                      uint32_t addr) {
    asm volatile("ldmatrix.sync.aligned.m8n8.x4.shared.b16 {%0,%1,%2,%3}, [%4];"
        : "=r"(r0), "=r"(r1), "=r"(r2), "=r"(r3) : "r"(addr));
}
__device__ __forceinline__ void mma_bf16(float4& c,
                                         uint32_t a0, uint32_t a1, uint32_t a2, uint32_t a3,
                                         uint32_t b0, uint32_t b1) {
    asm volatile(
        "mma.sync.aligned.m16n8k16.row.col.f32.bf16.bf16.f32 "
        "{%0,%1,%2,%3}, {%4,%5,%6,%7}, {%8,%9}, {%0,%1,%2,%3};"
        : "+f"(c.x), "+f"(c.y), "+f"(c.z), "+f"(c.w)
        : "r"(a0), "r"(a1), "r"(a2), "r"(a3), "r"(b0), "r"(b1));
}

// ---------------------------------------------------------------------------
// Prep: split feature into bf16 hi/lo packed words
// ---------------------------------------------------------------------------
__global__ void split_feat_kernel(const float* __restrict__ f) {
    int idx = blockIdx.x * 256 + threadIdx.x;            // float4 index
    float4 x = reinterpret_cast<const float4*>(f)[idx];
    uint32_t h0 = bf16rn(x.x), h1 = bf16rn(x.y), h2 = bf16rn(x.z), h3 = bf16rn(x.w);
    uint32_t l0 = bf16rn(x.x - bf16f(h0)), l1 = bf16rn(x.y - bf16f(h1));
    uint32_t l2 = bf16rn(x.z - bf16f(h2)), l3 = bf16rn(x.w - bf16f(h3));
    g_a_hi[idx * 2]     = h0 | (h1 << 16);
    g_a_hi[idx * 2 + 1] = h2 | (h3 << 16);
    g_a_lo[idx * 2]     = l0 | (l1 << 16);
    g_a_lo[idx * 2 + 1] = l2 | (l3 << 16);
}

// W1 [o][k][n] fp32 -> [o][n][k/2] packed bf16 hi/lo
__global__ void transpose_w1_kernel(const float* __restrict__ W1) {
    __shared__ float tile[32][33];
    const int o = blockIdx.z;
    const int n0 = blockIdx.x * 32, k0 = blockIdx.y * 32;
    const float* s = W1 + (size_t)o * INF * H1D;
    const int tx = threadIdx.x, ty = threadIdx.y;
#pragma unroll
    for (int i = 0; i < 32; i += 8)
        tile[ty + i][tx] = s[(size_t)(k0 + ty + i) * H1D + n0 + tx];
    __syncthreads();
#pragma unroll
    for (int i = 0; i < 2; i++) {
        int jp = ty + i * 8;                             // k-pair index 0..15
        float a = tile[2 * jp][tx], b = tile[2 * jp + 1][tx];
        uint32_t ha = bf16rn(a), hb = bf16rn(b);
        uint32_t la = bf16rn(a - bf16f(ha)), lb = bf16rn(b - bf16f(hb));
        size_t di = ((size_t)o * H1D + n0 + tx) * (INF / 2) + (k0 >> 1) + jp;
        g_w1_hi[di] = ha | (hb << 16);
        g_w1_lo[di] = la | (lb << 16);
    }
}

__global__ void zero_counts_kernel() {
    if (threadIdx.x < NT) g_count[threadIdx.x] = 0;
}
__global__ void route_kernel(const int* __restrict__ treatment) {
    int b = blockIdx.x * blockDim.x + threadIdx.x;
    if (b < Bsz) {
        int t = treatment[b];
        int p = atomicAdd(&g_count[t], 1);
        g_list[t * Bsz + p] = b;
    }
}
__global__ void combine_kernel(const int* __restrict__ treatment,
                               const float* __restrict__ b3,
                               float* __restrict__ out) {
    int i = blockIdx.x * 256 + threadIdx.x;   // i = b*NO + o
    int o = i & 3, b = i >> 2;
    int t = treatment[b];
    out[i] = g_part[(size_t)(o * 2 + 0) * Bsz + b]
           + g_part[(size_t)(o * 2 + 1) * Bsz + b]
           + b3[o * NT + t];
}

// ---------------------------------------------------------------------------
// Stage 1 via mma.sync bf16x3: h[o] = BN1(relu(feat @ W1[o] + b1)), fp32 out.
// CTA 128(M) x 64(N), 256 thr = 8 warps (4m x 2n), warp 32x32, K=512 by 32.
// Smem per buffer: A_hi 8K | A_lo 8K | B_hi 4K | B_lo 4K = 24K; x2 = 48K.
// Rows 64 B; chunk c of row r at r*64 + ((c*16) ^ ((r&3)<<4)).
// ---------------------------------------------------------------------------
__device__ __forceinline__ void s1_load_block(
    uint32_t sb, uint32_t bufoff, int tid, uint32_t k0b,
    const char* aH, const char* aL, const char* bH, const char* bL,
    size_t aOff0, size_t aOff1)
{
    const uint32_t bufb = sb + bufoff;
    const uint32_t gc = (uint32_t)(tid & 3) * 16u;
    const int r0 = tid >> 2;
    const int r1 = 64 + r0;
    const uint32_t o0 = (uint32_t)r0 * 64u + (gc ^ (((uint32_t)(r0 & 3)) << 4));
    const uint32_t o1 = (uint32_t)r1 * 64u + (gc ^ (((uint32_t)(r1 & 3)) << 4));
    cp_async16u(bufb + o0,          aH + aOff0 + k0b + gc);
    cp_async16u(bufb + 8192u + o0,  aL + aOff0 + k0b + gc);
    cp_async16u(bufb + o1,          aH + aOff1 + k0b + gc);
    cp_async16u(bufb + 8192u + o1,  aL + aOff1 + k0b + gc);
    cp_async16u(bufb + 16384u + o0, bH + (size_t)r0 * 1024 + k0b + gc);
    cp_async16u(bufb + 20480u + o0, bL + (size_t)r0 * 1024 + k0b + gc);
    cp_commit();
}

__global__ void __launch_bounds__(256) stage1_mma(
    const float* __restrict__ b1, const float* __restrict__ g1,
    const float* __restrict__ be1, const float* __restrict__ m1,
    const float* __restrict__ v1)
{
    __shared__ __align__(1024) char sm[49152];
    const uint32_t sb = smem_u32(sm);

    const int tid = threadIdx.x;
    const int lane = tid & 31, wid = tid >> 5;
    const int warp_m = wid & 3, warp_n = wid >> 2;
    const int lane_r = lane & 15;
    const uint32_t ksel = (uint32_t)((lane >> 4) << 4);
    const int quad_r = lane >> 2, quad_c = lane & 3;
    const int o = blockIdx.z, m0 = blockIdx.y * 128, n0 = blockIdx.x * 64;

    const char* aH = (const char*)g_a_hi + (size_t)m0 * 1024;
    const char* aL = (const char*)g_a_lo + (size_t)m0 * 1024;
    const char* bH = (const char*)g_w1_hi + ((size_t)o * H1D + n0) * 1024;
    const char* bL = (const char*)g_w1_lo + ((size_t)o * H1D + n0) * 1024;
    const size_t aOff0 = (size_t)(tid >> 2) * 1024;
    const size_t aOff1 = (size_t)(64 + (tid >> 2)) * 1024;

    const int ar0 = warp_m * 32 + lane_r, ar1 = ar0 + 16;
    const uint32_t aO0 = (uint32_t)ar0 * 64u, aX0 = (uint32_t)((ar0 & 3) << 4);
    const uint32_t aO1 = (uint32_t)ar1 * 64u, aX1 = (uint32_t)((ar1 & 3) << 4);
    const int br0 = warp_n * 32 + lane_r, br1 = br0 + 16;
    const uint32_t bO0 = (uint32_t)br0 * 64u, bX0 = (uint32_t)((br0 & 3) << 4);
    const uint32_t bO1 = (uint32_t)br1 * 64u, bX1 = (uint32_t)((br1 & 3) << 4);

    float4 c00 = make_float4(0.f, 0.f, 0.f, 0.f), c01 = c00, c02 = c00, c03 = c00;
    float4 c10 = c00, c11 = c00, c12 = c00, c13 = c00;

    s1_load_block(sb, 0u,      tid, 0u,  aH, aL, bH, bL, aOff0, aOff1);
    s1_load_block(sb, 24576u,  tid, 64u, aH, aL, bH, bL, aOff0, aOff1);

    for (int kb = 0; kb < 16; kb++) {
        const uint32_t bufb = sb + (uint32_t)(kb & 1) * 24576u;
        if (kb == 15) cp_wait<0>(); else cp_wait<1>();
        __syncthreads();
#pragma unroll
        for (int st = 0; st < 2; st++) {
            const uint32_t cb = (uint32_t)(st * 32) + ksel;
            uint32_t bh00, bh01, bh02, bh03, bh10, bh11, bh12, bh13;
            uint32_t bl00, bl01, bl02, bl03, bl10, bl11, bl12, bl13;
            ldmx4(bh00, bh01, bh02, bh03, bufb + 16384u + bO0 + (cb ^ bX0));
            ldmx4(bh10, bh11, bh12, bh13, bufb + 16384u + bO1 + (cb ^ bX1));
            ldmx4(bl00, bl01, bl02, bl03, bufb + 20480u + bO0 + (cb ^ bX0));
            ldmx4(bl10, bl11, bl12, bl13, bufb + 20480u + bO1 + (cb ^ bX1));
            // im = 0
            {
                uint32_t ah0, ah1, ah2, ah3, al0, al1, al2, al3;
                ldmx4(ah0, ah1, ah2, ah3, bufb + aO0 + (cb ^ aX0));
                ldmx4(al0, al1, al2, al3, bufb + 8192u + aO0 + (cb ^ aX0));
                mma_bf16(c00, ah0, ah1, ah2, ah3, bh00, bh02);
                mma_bf16(c00, ah0, ah1, ah2, ah3, bl00, bl02);
                mma_bf16(c00, al0, al1, al2, al3, bh00, bh02);
                mma_bf16(c01, ah0, ah1, ah2, ah3, bh01, bh03);
                mma_bf16(c01, ah0, ah1, ah2, ah3, bl01, bl03);
                mma_bf16(c01, al0, al1, al2, al3, bh01, bh03);
                mma_bf16(c02, ah0, ah1, ah2, ah3, bh10, bh12);
                mma_bf16(c02, ah0, ah1, ah2, ah3, bl10, bl12);
                mma_bf16(c02, al0, al1, al2, al3, bh10, bh12);
                mma_bf16(c03, ah0, ah1, ah2, ah3, bh11, bh13);
                mma_bf16(c03, ah0, ah1, ah2, ah3, bl11, bl13);
                mma_bf16(c03, al0, al1, al2, al3, bh11, bh13);
            }
            // im = 1
            {
                uint32_t ah0, ah1, ah2, ah3, al0, al1, al2, al3;
                ldmx4(ah0, ah1, ah2, ah3, bufb + aO1 + (cb ^ aX1));
                ldmx4(al0, al1, al2, al3, bufb + 8192u + aO1 + (cb ^ aX1));
                mma_bf16(c10, ah0, ah1, ah2, ah3, bh00, bh02);
                mma_bf16(c10, ah0, ah1, ah2, ah3, bl00, bl02);
                mma_bf16(c10, al0, al1, al2, al3, bh00, bh02);
                mma_bf16(c11, ah0, ah1, ah2, ah3, bh01, bh03);
                mma_bf16(c11, ah0, ah1, ah2, ah3, bl01, bl03);
                mma_bf16(c11, al0, al1, al2, al3, bh01, bh03);
                mma_bf16(c12, ah0, ah1, ah2, ah3, bh10, bh12);
                mma_bf16(c12, ah0, ah1, ah2, ah3, bl10, bl12);
                mma_bf16(c12, al0, al1, al2, al3, bh10, bh12);
                mma_bf16(c13, ah0, ah1, ah2, ah3, bh11, bh13);
                mma_bf16(c13, ah0, ah1, ah2, ah3, bl11, bl13);
                mma_bf16(c13, al0, al1, al2, al3, bh11, bh13);
            }
        }
        __syncthreads();
        if (kb + 2 < 16)
            s1_load_block(sb, (uint32_t)(kb & 1) * 24576u, tid, (uint32_t)(kb + 2) * 64u,
                          aH, aL, bH, bL, aOff0, aOff1);
    }

    // Epilogue: bias + relu + BN affine, store fp32 h
    float sc[4][2], sh[4][2], bb[4][2];
#pragma unroll
    for (int in = 0; in < 4; in++)
#pragma unroll
        for (int j = 0; j < 2; j++) {
            int cidx = o * H1D + n0 + warp_n * 32 + in * 8 + quad_c * 2 + j;
            float scale = g1[cidx] * rsqrtf(v1[cidx] + EPSV);
            sc[in][j] = scale;
            sh[in][j] = be1[cidx] - m1[cidx] * scale;
            bb[in][j] = b1[cidx];
        }
    const size_t hbase = (size_t)o * Bsz;
#pragma unroll
    for (int im = 0; im < 2; im++) {
#pragma unroll
        for (int in = 0; in < 4; in++) {
            float4 c = (im == 0)
                ? (in == 0 ? c00 : in == 1 ? c01 : in == 2 ? c02 : c03)
                : (in == 0 ? c10 : in == 1 ? c11 : in == 2 ? c12 : c13);
            const int cl = n0 + warp_n * 32 + in * 8 + quad_c * 2;
            {   // h = 0 rows
                int row = m0 + warp_m * 32 + im * 16 + quad_r;
                float v0 = fmaxf(c.x + bb[in][0], 0.f) * sc[in][0] + sh[in][0];
                float v1f = fmaxf(c.y + bb[in][1], 0.f) * sc[in][1] + sh[in][1];
                g_h[(hbase + row) * H1D + cl]     = v0;
                g_h[(hbase + row) * H1D + cl + 1] = v1f;
            }
            {   // h = 1 rows (+8)
                int row = m0 + warp_m * 32 + im * 16 + quad_r + 8;
                float v0 = fmaxf(c.z + bb[in][0], 0.f) * sc[in][0] + sh[in][0];
                float v1f = fmaxf(c.w + bb[in][1], 0.f) * sc[in][1] + sh[in][1];
                g_h[(hbase + row) * H1D + cl]     = v0;
                g_h[(hbase + row) * H1D + cl + 1] = v1f;
            }
        }
    }
}

// ---------------------------------------------------------------------------
// Stage 2 (verbatim from the passing round-9 kernel): fp32 SIMT GEMM.
// ---------------------------------------------------------------------------
__global__ void __launch_bounds__(256, 2) stage2_real(
    const float* __restrict__ W2, const float* __restrict__ b2,
    const float* __restrict__ g2, const float* __restrict__ be2,
    const float* __restrict__ m2, const float* __restrict__ v2,
    const float* __restrict__ W3)
{
    const int o = blockIdx.z;
    const int t = blockIdx.y >> 1, nh = blockIdx.y & 1;
    const int cnt = g_count[t];
    const int m0 = blockIdx.x * 128;
    if (m0 >= cnt) return;

    __shared__ __align__(16) float As[2][16][132];
    __shared__ __align__(16) float Bs[2][16][132];
    __shared__ int gidx[128];

    const int tid = threadIdx.x;
    const int tm = tid >> 4, tn = tid & 15;
    const int head = o * NT + t;
    const int n0 = nh * 128;

    if (tid < 128) {
        int r = m0 + tid;
        gidx[tid] = g_list[t * Bsz + (r < cnt ? r : cnt - 1)];
    }
    __syncthreads();

    const float* aBase = g_h + (size_t)o * Bsz * H1D;
    const float* bSrc = W2 + ((size_t)head * H1D) * H2D + n0;

    const int lr0 = tid >> 2;
    const int lr1 = 64 + lr0;
    const int lc4 = (tid & 3) * 4;
    const size_t aOff0 = (size_t)gidx[lr0] * H1D;
    const size_t aOff1 = (size_t)gidx[lr1] * H1D;

    float4 aReg0, aReg1;
    aReg0 = *reinterpret_cast<const float4*>(aBase + aOff0 + lc4);
    aReg1 = *reinterpret_cast<const float4*>(aBase + aOff1 + lc4);
    {
        int kk = tid >> 5, c = tid & 31;
        cp_async16(&Bs[0][kk][c * 4], bSrc + (size_t)kk * H2D + c * 4);
        cp_async16(&Bs[0][kk + 8][c * 4], bSrc + (size_t)(kk + 8) * H2D + c * 4);
        cp_commit();
    }
    As[0][lc4 + 0][lr0] = aReg0.x; As[0][lc4 + 1][lr0] = aReg0.y;
    As[0][lc4 + 2][lr0] = aReg0.z; As[0][lc4 + 3][lr0] = aReg0.w;
    As[0][lc4 + 0][lr1] = aReg1.x; As[0][lc4 + 1][lr1] = aReg1.y;
    As[0][lc4 + 2][lr1] = aReg1.z; As[0][lc4 + 3][lr1] = aReg1.w;
    aReg0 = *reinterpret_cast<const float4*>(aBase + aOff0 + 16 + lc4);
    aReg1 = *reinterpret_cast<const float4*>(aBase + aOff1 + 16 + lc4);
    {
        int kk = tid >> 5, c = tid & 31;
        cp_async16(&Bs[1][kk][c * 4], bSrc + (size_t)(16 + kk) * H2D + c * 4);
        cp_async16(&Bs[1][kk + 8][c * 4], bSrc + (size_t)(24 + kk) * H2D + c * 4);
        cp_commit();
    }
    As[1][lc4 + 0][lr0] = aReg0.x; As[1][lc4 + 1][lr0] = aReg0.y;
    As[1][lc4 + 2][lr0] = aReg0.z; As[1][lc4 + 3][lr0] = aReg0.w;
    As[1][lc4 + 0][lr1] = aReg1.x; As[1][lc4 + 1][lr1] = aReg1.y;
    As[1][lc4 + 2][lr1] = aReg1.z; As[1][lc4 + 3][lr1] = aReg1.w;
    aReg0 = *reinterpret_cast<const float4*>(aBase + aOff0 + 32 + lc4);
    aReg1 = *reinterpret_cast<const float4*>(aBase + aOff1 + 32 + lc4);

    float acc[8][8];
#pragma unroll
    for (int i = 0; i < 8; i++)
#pragma unroll
        for (int j = 0; j < 8; j++) acc[i][j] = 0.f;

    for (int kb = 0; kb < 32; kb++) {
        const int buf = kb & 1;
        if (kb >= 30) cp_wait<0>(); else cp_wait<1>();
        __syncthreads();
#pragma unroll
        for (int kk = 0; kk < 16; kk++) {
            float af[8], bf[8];
            *reinterpret_cast<float4*>(&af[0]) = *reinterpret_cast<const float4*>(&As[buf][kk][tm * 8]);
            *reinterpret_cast<float4*>(&af[4]) = *reinterpret_cast<const float4*>(&As[buf][kk][tm * 8 + 4]);
            *reinterpret_cast<float4*>(&bf[0]) = *reinterpret_cast<const float4*>(&Bs[buf][kk][tn * 8]);
            *reinterpret_cast<float4*>(&bf[4]) = *reinterpret_cast<const float4*>(&Bs[buf][kk][tn * 8 + 4]);
#pragma unroll
            for (int i = 0; i < 8; i++)
#pragma unroll
                for (int j = 0; j < 8; j++) acc[i][j] = fmaf(af[i], bf[j], acc[i][j]);
        }
        __syncthreads();
        if (kb + 2 < 32) {
            As[buf][lc4 + 0][lr0] = aReg0.x; As[buf][lc4 + 1][lr0] = aReg0.y;
            As[buf][lc4 + 2][lr0] = aReg0.z; As[buf][lc4 + 3][lr0] = aReg0.w;
            As[buf][lc4 + 0][lr1] = aReg1.x; As[buf][lc4 + 1][lr1] = aReg1.y;
            As[buf][lc4 + 2][lr1] = aReg1.z; As[buf][lc4 + 3][lr1] = aReg1.w;
            int kk = tid >> 5, c = tid & 31;
            int kbase = (kb + 2) * 16;
            cp_async16(&Bs[buf][kk][c * 4], bSrc + (size_t)(kbase + kk) * H2D + c * 4);
            cp_async16(&Bs[buf][kk + 8][c * 4], bSrc + (size_t)(kbase + kk + 8) * H2D + c * 4);
            cp_commit();
            if (kb + 3 < 32) {
                int knext = (kb + 3) * 16;
                aReg0 = *reinterpret_cast<const float4*>(aBase + aOff0 + knext + lc4);
                aReg1 = *reinterpret_cast<const float4*>(aBase + aOff1 + knext + lc4);
            }
        }
    }

    float sc[8], sh[8], bb[8], w3[8];
#pragma unroll
    for (int j = 0; j < 8; j++) {
        int idx = head * H2D + n0 + tn * 8 + j;
        float s = g2[idx] * rsqrtf(v2[idx] + EPSV);
        sc[j] = s;
        sh[j] = be2[idx] - m2[idx] * s;
        bb[j] = b2[idx];
        w3[j] = W3[idx];
    }
#pragma unroll
    for (int i = 0; i < 8; i++) {
        float part = 0.f;
#pragma unroll
        for (int j = 0; j < 8; j++) {
            float z = fmaxf(acc[i][j] + bb[j], 0.f) * sc[j] + sh[j];
            part = fmaf(z, w3[j], part);
        }
        part += __shfl_xor_sync(0xffffffffu, part, 1);
        part += __shfl_xor_sync(0xffffffffu, part, 2);
        part += __shfl_xor_sync(0xffffffffu, part, 4);
        part += __shfl_xor_sync(0xffffffffu, part, 8);
        if (tn == 0) {
            int rl = tm * 8 + i;
            if (m0 + rl < cnt) {
                g_part[(size_t)(o * 2 + nh) * Bsz + gidx[rl]] = part;
            }
        }
    }
}

// ---------------------------------------------------------------------------
extern "C" void kernel_launch(void* const* d_in, const int* in_sizes, int n_in,
                              void* d_out, int out_size)
{
    const float* feature   = (const float*)d_in[0];
    const int*   treatment = (const int*)  d_in[1];
    const float* W1  = (const float*)d_in[2];
    const float* b1  = (const float*)d_in[3];
    const float* g1  = (const float*)d_in[4];
    const float* be1 = (const float*)d_in[5];
    const float* m1  = (const float*)d_in[6];
    const float* v1  = (const float*)d_in[7];
    const float* W2  = (const float*)d_in[8];
    const float* b2  = (const float*)d_in[9];
    const float* g2  = (const float*)d_in[10];
    const float* be2 = (const float*)d_in[11];
    const float* m2  = (const float*)d_in[12];
    const float* v2  = (const float*)d_in[13];
    const float* W3  = (const float*)d_in[14];
    const float* b3  = (const float*)d_in[15];
    float* out = (float*)d_out;

    split_feat_kernel<<<(Bsz * INF) / (256 * 4), 256>>>(feature);
    transpose_w1_kernel<<<dim3(H1D / 32, INF / 32, NO), dim3(32, 8)>>>(W1);
    zero_counts_kernel<<<1, 32>>>();
    route_kernel<<<Bsz / 256, 256>>>(treatment);
    stage1_mma<<<dim3(H1D / 64, Bsz / 128, NO), 256>>>(b1, g1, be1, m1, v1);
    stage2_real<<<dim3(Bsz / 128, NT * 2, NO), 256>>>(W2, b2, g2, be2, m2, v2, W3);
    combine_kernel<<<(Bsz * NO) / 256, 256>>>(treatment, b3, out);
}

// round 17
// speedup vs baseline: 1.8346x; 1.2217x over previous
#include <cuda_runtime.h>
#include <stdint.h>

#define Bsz 16384
#define INF 512
#define H1D 512
#define H2D 256
#define NO 4
#define NT 4
#define EPSV 1e-5f

// ---------------------------------------------------------------------------
// Device scratch. bf16 packed 2-per-uint32; no cuda_bf16.h.
// CRITICAL RULE (rounds 4-8, 11-15 post-mortem): __device__ globals are NEVER
// passed as kernel arguments from host code — host-side symbol addresses are
// HMM-accessible host shadows, and first-touch carves a 128 MiB device-side
// migration arena that trips the harness memory guard. All global access is
// by direct symbol reference inside device code.
// ---------------------------------------------------------------------------
__device__ uint32_t g_a_hi[(size_t)Bsz * INF / 2];           // 16 MiB
__device__ uint32_t g_a_lo[(size_t)Bsz * INF / 2];           // 16 MiB
__device__ uint32_t g_w1_hi[(size_t)NO * H1D * INF / 2];     // 2 MiB [o][n][k/2]
__device__ uint32_t g_w1_lo[(size_t)NO * H1D * INF / 2];     // 2 MiB
__device__ uint32_t g_w2_hi[(size_t)NO * NT * H2D * H1D / 2];// 4 MiB [head][n][k/2]
__device__ uint32_t g_w2_lo[(size_t)NO * NT * H2D * H1D / 2];// 4 MiB
__device__ uint32_t g_h_hi[(size_t)NO * Bsz * H1D / 2];      // 64 MiB [o][b][k/2]
__device__ uint32_t g_h_lo[(size_t)NO * Bsz * H1D / 2];      // 64 MiB
__device__ float    g_part[(size_t)NO * 8 * Bsz];            // 2 MiB [o][slot][b]
__device__ int      g_list[NT * Bsz];
__device__ int      g_count[NT];

// ---------------------------------------------------------------------------
// Helpers
// ---------------------------------------------------------------------------
__device__ __forceinline__ uint32_t bf16rn(float f) {     // RNE, low 16 bits
    uint32_t u = __float_as_uint(f);
    return (u + 0x7FFFu + ((u >> 16) & 1u)) >> 16;
}
__device__ __forceinline__ float bf16f(uint32_t h) { return __uint_as_float(h << 16); }

__device__ __forceinline__ uint32_t smem_u32(const void* p) {
    return (uint32_t)__cvta_generic_to_shared(p);
}
__device__ __forceinline__ void cp_async16u(uint32_t saddr, const void* gmem) {
    asm volatile("cp.async.ca.shared.global [%0], [%1], 16;" :: "r"(saddr), "l"(gmem));
}
__device__ __forceinline__ void cp_commit() { asm volatile("cp.async.commit_group;"); }
template <int N>
__device__ __forceinline__ void cp_wait() { asm volatile("cp.async.wait_group %0;" :: "n"(N)); }

__device__ __forceinline__ void ldmx4(uint32_t& r0, uint32_t& r1, uint32_t& r2, uint32_t& r3,
                                      uint32_t addr) {
    asm volatile("ldmatrix.sync.aligned.m8n8.x4.shared.b16 {%0,%1,%2,%3}, [%4];"
        : "=r"(r0), "=r"(r1), "=r"(r2), "=r"(r3) : "r"(addr));
}
__device__ __forceinline__ void mma_bf16(float4& c,
                                         uint32_t a0, uint32_t a1, uint32_t a2, uint32_t a3,
                                         uint32_t b0, uint32_t b1) {
    asm volatile(
        "mma.sync.aligned.m16n8k16.row.col.f32.bf16.bf16.f32 "
        "{%0,%1,%2,%3}, {%4,%5,%6,%7}, {%8,%9}, {%0,%1,%2,%3};"
        : "+f"(c.x), "+f"(c.y), "+f"(c.z), "+f"(c.w)
        : "r"(a0), "r"(a1), "r"(a2), "r"(a3), "r"(b0), "r"(b1));
}

// ---------------------------------------------------------------------------
// Prep kernels (write fixed __device__ globals directly; no symbol args)
// ---------------------------------------------------------------------------
__global__ void split_feat_kernel(const float* __restrict__ f) {
    int idx = blockIdx.x * 256 + threadIdx.x;            // float4 index
    float4 x = reinterpret_cast<const float4*>(f)[idx];
    uint32_t h0 = bf16rn(x.x), h1 = bf16rn(x.y), h2 = bf16rn(x.z), h3 = bf16rn(x.w);
    uint32_t l0 = bf16rn(x.x - bf16f(h0)), l1 = bf16rn(x.y - bf16f(h1));
    uint32_t l2 = bf16rn(x.z - bf16f(h2)), l3 = bf16rn(x.w - bf16f(h3));
    g_a_hi[idx * 2]     = h0 | (h1 << 16);
    g_a_hi[idx * 2 + 1] = h2 | (h3 << 16);
    g_a_lo[idx * 2]     = l0 | (l1 << 16);
    g_a_lo[idx * 2 + 1] = l2 | (l3 << 16);
}

// W1 [o][k][n] fp32 -> g_w1 [o][n][k/2] packed bf16 hi/lo (R10-proven pattern)
__global__ void transpose_w1_kernel(const float* __restrict__ W1) {
    __shared__ float tile[32][33];
    const int o = blockIdx.z;
    const int n0 = blockIdx.x * 32, k0 = blockIdx.y * 32;
    const float* s = W1 + (size_t)o * INF * H1D;
    const int tx = threadIdx.x, ty = threadIdx.y;
#pragma unroll
    for (int i = 0; i < 32; i += 8)
        tile[ty + i][tx] = s[(size_t)(k0 + ty + i) * H1D + n0 + tx];
    __syncthreads();
#pragma unroll
    for (int i = 0; i < 2; i++) {
        int jp = ty + i * 8;
        float a = tile[2 * jp][tx], b = tile[2 * jp + 1][tx];
        uint32_t ha = bf16rn(a), hb = bf16rn(b);
        uint32_t la = bf16rn(a - bf16f(ha)), lb = bf16rn(b - bf16f(hb));
        size_t di = ((size_t)o * H1D + n0 + tx) * (INF / 2) + (k0 >> 1) + jp;
        g_w1_hi[di] = ha | (hb << 16);
        g_w1_lo[di] = la | (lb << 16);
    }
}

// W2 [head][k(H1D)][n(H2D)] fp32 -> g_w2 [head][n][k/2] packed bf16 hi/lo
__global__ void transpose_w2_kernel(const float* __restrict__ W2) {
    __shared__ float tile[32][33];
    const int hd = blockIdx.z;
    const int n0 = blockIdx.x * 32, k0 = blockIdx.y * 32;
    const float* s = W2 + (size_t)hd * H1D * H2D;
    const int tx = threadIdx.x, ty = threadIdx.y;
#pragma unroll
    for (int i = 0; i < 32; i += 8)
        tile[ty + i][tx] = s[(size_t)(k0 + ty + i) * H2D + n0 + tx];
    __syncthreads();
#pragma unroll
    for (int i = 0; i < 2; i++) {
        int jp = ty + i * 8;
        float a = tile[2 * jp][tx], b = tile[2 * jp + 1][tx];
        uint32_t ha = bf16rn(a), hb = bf16rn(b);
        uint32_t la = bf16rn(a - bf16f(ha)), lb = bf16rn(b - bf16f(hb));
        size_t di = ((size_t)hd * H2D + n0 + tx) * (H1D / 2) + (k0 >> 1) + jp;
        g_w2_hi[di] = ha | (hb << 16);
        g_w2_lo[di] = la | (lb << 16);
    }
}

__global__ void zero_counts_kernel() {
    if (threadIdx.x < NT) g_count[threadIdx.x] = 0;
}
__global__ void route_kernel(const int* __restrict__ treatment) {
    int b = blockIdx.x * blockDim.x + threadIdx.x;
    if (b < Bsz) {
        int t = treatment[b];
        int p = atomicAdd(&g_count[t], 1);
        g_list[t * Bsz + p] = b;
    }
}
// out[b][o] = sum_{slot 0..7} g_part[o][slot][b] + b3[o][t[b]]  (fixed order)
__global__ void combine_kernel(const int* __restrict__ treatment,
                               const float* __restrict__ b3,
                               float* __restrict__ out) {
    int i = blockIdx.x * 256 + threadIdx.x;   // i = b*NO + o
    int o = i & 3, b = i >> 2;
    int t = treatment[b];
    const float* p = g_part + (size_t)o * 8 * Bsz + b;
    float v = 0.f;
#pragma unroll
    for (int s = 0; s < 8; s++) v += p[(size_t)s * Bsz];
    out[i] = v + b3[o * NT + t];
}

// Shared loader: A 128 rows x 64B (hi+lo), B 64 rows x 64B (hi+lo).
// Rows 64 B; chunk c of row r at r*64 + ((c*16) ^ ((r&3)<<4)).
__device__ __forceinline__ void load_block64(
    uint32_t bufb, int tid, uint32_t k0b,
    const char* aH, const char* aL, const char* bH, const char* bL,
    size_t aOff0, size_t aOff1)
{
    const uint32_t gc = (uint32_t)(tid & 3) * 16u;
    const int r0 = tid >> 2;
    const int r1 = 64 + r0;
    const uint32_t o0 = (uint32_t)r0 * 64u + (gc ^ (((uint32_t)(r0 & 3)) << 4));
    const uint32_t o1 = (uint32_t)r1 * 64u + (gc ^ (((uint32_t)(r1 & 3)) << 4));
    cp_async16u(bufb + o0,          aH + aOff0 + k0b + gc);
    cp_async16u(bufb + 8192u + o0,  aL + aOff0 + k0b + gc);
    cp_async16u(bufb + o1,          aH + aOff1 + k0b + gc);
    cp_async16u(bufb + 8192u + o1,  aL + aOff1 + k0b + gc);
    cp_async16u(bufb + 16384u + o0, bH + (size_t)r0 * 1024 + k0b + gc);
    cp_async16u(bufb + 20480u + o0, bL + (size_t)r0 * 1024 + k0b + gc);
    cp_commit();
}

// ---------------------------------------------------------------------------
// Stage 1 via mma.sync bf16x3: h[o] = BN1(relu(feat @ W1[o] + b1)),
// output packed bf16 hi/lo. CTA 128x64, 8 warps (4m x 2n), K=512 by 32.
// ---------------------------------------------------------------------------
__global__ void __launch_bounds__(256) stage1_mma(
    const float* __restrict__ b1, const float* __restrict__ g1,
    const float* __restrict__ be1, const float* __restrict__ m1,
    const float* __restrict__ v1)
{
    __shared__ __align__(1024) char sm[49152];
    const uint32_t sb = smem_u32(sm);

    const int tid = threadIdx.x;
    const int lane = tid & 31, wid = tid >> 5;
    const int warp_m = wid & 3, warp_n = wid >> 2;
    const int lane_r = lane & 15;
    const uint32_t ksel = (uint32_t)((lane >> 4) << 4);
    const int quad_r = lane >> 2, quad_c = lane & 3;
    const int o = blockIdx.z, m0 = blockIdx.y * 128, n0 = blockIdx.x * 64;

    const char* aH = (const char*)g_a_hi + (size_t)m0 * 1024;
    const char* aL = (const char*)g_a_lo + (size_t)m0 * 1024;
    const char* bH = (const char*)g_w1_hi + ((size_t)o * H1D + n0) * 1024;
    const char* bL = (const char*)g_w1_lo + ((size_t)o * H1D + n0) * 1024;
    const size_t aOff0 = (size_t)(tid >> 2) * 1024;
    const size_t aOff1 = (size_t)(64 + (tid >> 2)) * 1024;

    const int ar0 = warp_m * 32 + lane_r, ar1 = ar0 + 16;
    const uint32_t aO0 = (uint32_t)ar0 * 64u, aX0 = (uint32_t)((ar0 & 3) << 4);
    const uint32_t aO1 = (uint32_t)ar1 * 64u, aX1 = (uint32_t)((ar1 & 3) << 4);
    const int br0 = warp_n * 32 + lane_r, br1 = br0 + 16;
    const uint32_t bO0 = (uint32_t)br0 * 64u, bX0 = (uint32_t)((br0 & 3) << 4);
    const uint32_t bO1 = (uint32_t)br1 * 64u, bX1 = (uint32_t)((br1 & 3) << 4);

    float4 c00 = make_float4(0.f, 0.f, 0.f, 0.f), c01 = c00, c02 = c00, c03 = c00;
    float4 c10 = c00, c11 = c00, c12 = c00, c13 = c00;

    load_block64(sb,          tid, 0u,  aH, aL, bH, bL, aOff0, aOff1);
    load_block64(sb + 24576u, tid, 64u, aH, aL, bH, bL, aOff0, aOff1);

    for (int kb = 0; kb < 16; kb++) {
        const uint32_t bufb = sb + (uint32_t)(kb & 1) * 24576u;
        if (kb == 15) cp_wait<0>(); else cp_wait<1>();
        __syncthreads();
#pragma unroll
        for (int st = 0; st < 2; st++) {
            const uint32_t cb = (uint32_t)(st * 32) + ksel;
            uint32_t bh00, bh01, bh02, bh03, bh10, bh11, bh12, bh13;
            uint32_t bl00, bl01, bl02, bl03, bl10, bl11, bl12, bl13;
            ldmx4(bh00, bh01, bh02, bh03, bufb + 16384u + bO0 + (cb ^ bX0));
            ldmx4(bh10, bh11, bh12, bh13, bufb + 16384u + bO1 + (cb ^ bX1));
            ldmx4(bl00, bl01, bl02, bl03, bufb + 20480u + bO0 + (cb ^ bX0));
            ldmx4(bl10, bl11, bl12, bl13, bufb + 20480u + bO1 + (cb ^ bX1));
            {
                uint32_t ah0, ah1, ah2, ah3, al0, al1, al2, al3;
                ldmx4(ah0, ah1, ah2, ah3, bufb + aO0 + (cb ^ aX0));
                ldmx4(al0, al1, al2, al3, bufb + 8192u + aO0 + (cb ^ aX0));
                mma_bf16(c00, ah0, ah1, ah2, ah3, bh00, bh02);
                mma_bf16(c00, ah0, ah1, ah2, ah3, bl00, bl02);
                mma_bf16(c00, al0, al1, al2, al3, bh00, bh02);
                mma_bf16(c01, ah0, ah1, ah2, ah3, bh01, bh03);
                mma_bf16(c01, ah0, ah1, ah2, ah3, bl01, bl03);
                mma_bf16(c01, al0, al1, al2, al3, bh01, bh03);
                mma_bf16(c02, ah0, ah1, ah2, ah3, bh10, bh12);
                mma_bf16(c02, ah0, ah1, ah2, ah3, bl10, bl12);
                mma_bf16(c02, al0, al1, al2, al3, bh10, bh12);
                mma_bf16(c03, ah0, ah1, ah2, ah3, bh11, bh13);
                mma_bf16(c03, ah0, ah1, ah2, ah3, bl11, bl13);
                mma_bf16(c03, al0, al1, al2, al3, bh11, bh13);
            }
            {
                uint32_t ah0, ah1, ah2, ah3, al0, al1, al2, al3;
                ldmx4(ah0, ah1, ah2, ah3, bufb + aO1 + (cb ^ aX1));
                ldmx4(al0, al1, al2, al3, bufb + 8192u + aO1 + (cb ^ aX1));
                mma_bf16(c10, ah0, ah1, ah2, ah3, bh00, bh02);
                mma_bf16(c10, ah0, ah1, ah2, ah3, bl00, bl02);
                mma_bf16(c10, al0, al1, al2, al3, bh00, bh02);
                mma_bf16(c11, ah0, ah1, ah2, ah3, bh01, bh03);
                mma_bf16(c11, ah0, ah1, ah2, ah3, bl01, bl03);
                mma_bf16(c11, al0, al1, al2, al3, bh01, bh03);
                mma_bf16(c12, ah0, ah1, ah2, ah3, bh10, bh12);
                mma_bf16(c12, ah0, ah1, ah2, ah3, bl10, bl12);
                mma_bf16(c12, al0, al1, al2, al3, bh10, bh12);
                mma_bf16(c13, ah0, ah1, ah2, ah3, bh11, bh13);
                mma_bf16(c13, ah0, ah1, ah2, ah3, bl11, bl13);
                mma_bf16(c13, al0, al1, al2, al3, bh11, bh13);
            }
        }
        __syncthreads();
        if (kb + 2 < 16)
            load_block64(sb + (uint32_t)(kb & 1) * 24576u, tid, (uint32_t)(kb + 2) * 64u,
                         aH, aL, bH, bL, aOff0, aOff1);
    }

    // Epilogue: bias + relu + BN affine, pack bf16 hi/lo words of h.
    float sc[4][2], sh[4][2], bb[4][2];
#pragma unroll
    for (int in = 0; in < 4; in++)
#pragma unroll
        for (int j = 0; j < 2; j++) {
            int cidx = o * H1D + n0 + warp_n * 32 + in * 8 + quad_c * 2 + j;
            float scale = g1[cidx] * rsqrtf(v1[cidx] + EPSV);
            sc[in][j] = scale;
            sh[in][j] = be1[cidx] - m1[cidx] * scale;
            bb[in][j] = b1[cidx];
        }
    const size_t hbase = (size_t)o * Bsz;
#pragma unroll
    for (int im = 0; im < 2; im++) {
#pragma unroll
        for (int in = 0; in < 4; in++) {
            float4 c = (im == 0)
                ? (in == 0 ? c00 : in == 1 ? c01 : in == 2 ? c02 : c03)
                : (in == 0 ? c10 : in == 1 ? c11 : in == 2 ? c12 : c13);
            const int cl = n0 + warp_n * 32 + in * 8 + quad_c * 2;
            {
                int row = m0 + warp_m * 32 + im * 16 + quad_r;
                float v0 = fmaxf(c.x + bb[in][0], 0.f) * sc[in][0] + sh[in][0];
                float v1f = fmaxf(c.y + bb[in][1], 0.f) * sc[in][1] + sh[in][1];
                uint32_t h0 = bf16rn(v0), h1 = bf16rn(v1f);
                size_t widx = (hbase + row) * (H1D / 2) + (cl >> 1);
                g_h_hi[widx] = h0 | (h1 << 16);
                g_h_lo[widx] = bf16rn(v0 - bf16f(h0)) | (bf16rn(v1f - bf16f(h1)) << 16);
            }
            {
                int row = m0 + warp_m * 32 + im * 16 + quad_r + 8;
                float v0 = fmaxf(c.z + bb[in][0], 0.f) * sc[in][0] + sh[in][0];
                float v1f = fmaxf(c.w + bb[in][1], 0.f) * sc[in][1] + sh[in][1];
                uint32_t h0 = bf16rn(v0), h1 = bf16rn(v1f);
                size_t widx = (hbase + row) * (H1D / 2) + (cl >> 1);
                g_h_hi[widx] = h0 | (h1 << 16);
                g_h_lo[widx] = bf16rn(v0 - bf16f(h0)) | (bf16rn(v1f - bf16f(h1)) << 16);
            }
        }
    }
}

// ---------------------------------------------------------------------------
// Stage 2 via mma.sync bf16x3: per (o, t, nh): z = BN2(relu(h @ W2 slice)),
// partial = z . W3[slice]; write g_part[o][nh*2+warp_n][b].
// CTA 128 gathered rows x 64 cols, K=512 by 32.
// ---------------------------------------------------------------------------
__global__ void __launch_bounds__(256) stage2_mma(
    const float* __restrict__ b2, const float* __restrict__ g2,
    const float* __restrict__ be2, const float* __restrict__ m2,
    const float* __restrict__ v2, const float* __restrict__ W3)
{
    const int o = blockIdx.z;
    const int t = blockIdx.y >> 2, nh = blockIdx.y & 3;
    const int cnt = g_count[t];
    const int m0 = blockIdx.x * 128;
    if (m0 >= cnt) return;

    __shared__ __align__(1024) char sm[49152];
    const uint32_t sb = smem_u32(sm);

    const int tid = threadIdx.x;
    const int lane = tid & 31, wid = tid >> 5;
    const int warp_m = wid & 3, warp_n = wid >> 2;
    const int lane_r = lane & 15;
    const uint32_t ksel = (uint32_t)((lane >> 4) << 4);
    const int quad_r = lane >> 2, quad_c = lane & 3;
    const int head = o * NT + t;
    const int n0 = nh * 64;

    const char* aH = (const char*)g_h_hi + (size_t)o * Bsz * 1024;
    const char* aL = (const char*)g_h_lo + (size_t)o * Bsz * 1024;
    const char* bH = (const char*)g_w2_hi + ((size_t)head * H2D + n0) * 1024;
    const char* bL = (const char*)g_w2_lo + ((size_t)head * H2D + n0) * 1024;

    int lr0 = m0 + (tid >> 2);
    int lr1 = m0 + 64 + (tid >> 2);
    if (lr0 >= cnt) lr0 = cnt - 1;
    if (lr1 >= cnt) lr1 = cnt - 1;
    const size_t aOff0 = (size_t)g_list[t * Bsz + lr0] * 1024;
    const size_t aOff1 = (size_t)g_list[t * Bsz + lr1] * 1024;

    const int ar0 = warp_m * 32 + lane_r, ar1 = ar0 + 16;
    const uint32_t aO0 = (uint32_t)ar0 * 64u, aX0 = (uint32_t)((ar0 & 3) << 4);
    const uint32_t aO1 = (uint32_t)ar1 * 64u, aX1 = (uint32_t)((ar1 & 3) << 4);
    const int br0 = warp_n * 32 + lane_r, br1 = br0 + 16;
    const uint32_t bO0 = (uint32_t)br0 * 64u, bX0 = (uint32_t)((br0 & 3) << 4);
    const uint32_t bO1 = (uint32_t)br1 * 64u, bX1 = (uint32_t)((br1 & 3) << 4);

    float4 c00 = make_float4(0.f, 0.f, 0.f, 0.f), c01 = c00, c02 = c00, c03 = c00;
    float4 c10 = c00, c11 = c00, c12 = c00, c13 = c00;

    load_block64(sb,          tid, 0u,  aH, aL, bH, bL, aOff0, aOff1);
    load_block64(sb + 24576u, tid, 64u, aH, aL, bH, bL, aOff0, aOff1);

    for (int kb = 0; kb < 16; kb++) {
        const uint32_t bufb = sb + (uint32_t)(kb & 1) * 24576u;
        if (kb == 15) cp_wait<0>(); else cp_wait<1>();
        __syncthreads();
#pragma unroll
        for (int st = 0; st < 2; st++) {
            const uint32_t cb = (uint32_t)(st * 32) + ksel;
            uint32_t bh00, bh01, bh02, bh03, bh10, bh11, bh12, bh13;
            uint32_t bl00, bl01, bl02, bl03, bl10, bl11, bl12, bl13;
            ldmx4(bh00, bh01, bh02, bh03, bufb + 16384u + bO0 + (cb ^ bX0));
            ldmx4(bh10, bh11, bh12, bh13, bufb + 16384u + bO1 + (cb ^ bX1));
            ldmx4(bl00, bl01, bl02, bl03, bufb + 20480u + bO0 + (cb ^ bX0));
            ldmx4(bl10, bl11, bl12, bl13, bufb + 20480u + bO1 + (cb ^ bX1));
            {
                uint32_t ah0, ah1, ah2, ah3, al0, al1, al2, al3;
                ldmx4(ah0, ah1, ah2, ah3, bufb + aO0 + (cb ^ aX0));
                ldmx4(al0, al1, al2, al3, bufb + 8192u + aO0 + (cb ^ aX0));
                mma_bf16(c00, ah0, ah1, ah2, ah3, bh00, bh02);
                mma_bf16(c00, ah0, ah1, ah2, ah3, bl00, bl02);
                mma_bf16(c00, al0, al1, al2, al3, bh00, bh02);
                mma_bf16(c01, ah0, ah1, ah2, ah3, bh01, bh03);
                mma_bf16(c01, ah0, ah1, ah2, ah3, bl01, bl03);
                mma_bf16(c01, al0, al1, al2, al3, bh01, bh03);
                mma_bf16(c02, ah0, ah1, ah2, ah3, bh10, bh12);
                mma_bf16(c02, ah0, ah1, ah2, ah3, bl10, bl12);
                mma_bf16(c02, al0, al1, al2, al3, bh10, bh12);
                mma_bf16(c03, ah0, ah1, ah2, ah3, bh11, bh13);
                mma_bf16(c03, ah0, ah1, ah2, ah3, bl11, bl13);
                mma_bf16(c03, al0, al1, al2, al3, bh11, bh13);
            }
            {
                uint32_t ah0, ah1, ah2, ah3, al0, al1, al2, al3;
                ldmx4(ah0, ah1, ah2, ah3, bufb + aO1 + (cb ^ aX1));
                ldmx4(al0, al1, al2, al3, bufb + 8192u + aO1 + (cb ^ aX1));
                mma_bf16(c10, ah0, ah1, ah2, ah3, bh00, bh02);
                mma_bf16(c10, ah0, ah1, ah2, ah3, bl00, bl02);
                mma_bf16(c10, al0, al1, al2, al3, bh00, bh02);
                mma_bf16(c11, ah0, ah1, ah2, ah3, bh01, bh03);
                mma_bf16(c11, ah0, ah1, ah2, ah3, bl01, bl03);
                mma_bf16(c11, al0, al1, al2, al3, bh01, bh03);
                mma_bf16(c12, ah0, ah1, ah2, ah3, bh10, bh12);
                mma_bf16(c12, ah0, ah1, ah2, ah3, bl10, bl12);
                mma_bf16(c12, al0, al1, al2, al3, bh10, bh12);
                mma_bf16(c13, ah0, ah1, ah2, ah3, bh11, bh13);
                mma_bf16(c13, ah0, ah1, ah2, ah3, bl11, bl13);
                mma_bf16(c13, al0, al1, al2, al3, bh11, bh13);
            }
        }
        __syncthreads();
        if (kb + 2 < 16)
            load_block64(sb + (uint32_t)(kb & 1) * 24576u, tid, (uint32_t)(kb + 2) * 64u,
                         aH, aL, bH, bL, aOff0, aOff1);
    }

    // Epilogue: BN2+relu, dot W3 over warp's 32 cols, quad reduce, store partial.
    float sc[4][2], sh[4][2], bb[4][2], w3[4][2];
#pragma unroll
    for (int in = 0; in < 4; in++)
#pragma unroll
        for (int j = 0; j < 2; j++) {
            int cidx = head * H2D + n0 + warp_n * 32 + in * 8 + quad_c * 2 + j;
            float scale = g2[cidx] * rsqrtf(v2[cidx] + EPSV);
            sc[in][j] = scale;
            sh[in][j] = be2[cidx] - m2[cidx] * scale;
            bb[in][j] = b2[cidx];
            w3[in][j] = W3[cidx];
        }
    const int slot = nh * 2 + warp_n;
#pragma unroll
    for (int im = 0; im < 2; im++) {
#pragma unroll
        for (int h = 0; h < 2; h++) {
            float part = 0.f;
#pragma unroll
            for (int in = 0; in < 4; in++) {
                float4 c = (im == 0)
                    ? (in == 0 ? c00 : in == 1 ? c01 : in == 2 ? c02 : c03)
                    : (in == 0 ? c10 : in == 1 ? c11 : in == 2 ? c12 : c13);
                float e0 = (h == 0) ? c.x : c.z;
                float e1 = (h == 0) ? c.y : c.w;
                float z0 = fmaxf(e0 + bb[in][0], 0.f) * sc[in][0] + sh[in][0];
                float z1 = fmaxf(e1 + bb[in][1], 0.f) * sc[in][1] + sh[in][1];
                part = fmaf(z0, w3[in][0], part);
                part = fmaf(z1, w3[in][1], part);
            }
            part += __shfl_xor_sync(0xffffffffu, part, 1);
            part += __shfl_xor_sync(0xffffffffu, part, 2);
            if (quad_c == 0) {
                int rl = warp_m * 32 + im * 16 + quad_r + h * 8;
                if (m0 + rl < cnt) {
                    int gb = g_list[t * Bsz + m0 + rl];
                    g_part[((size_t)o * 8 + slot) * Bsz + gb] = part;
                }
            }
        }
    }
}

// ---------------------------------------------------------------------------
extern "C" void kernel_launch(void* const* d_in, const int* in_sizes, int n_in,
                              void* d_out, int out_size)
{
    const float* feature   = (const float*)d_in[0];
    const int*   treatment = (const int*)  d_in[1];
    const float* W1  = (const float*)d_in[2];
    const float* b1  = (const float*)d_in[3];
    const float* g1  = (const float*)d_in[4];
    const float* be1 = (const float*)d_in[5];
    const float* m1  = (const float*)d_in[6];
    const float* v1  = (const float*)d_in[7];
    const float* W2  = (const float*)d_in[8];
    const float* b2  = (const float*)d_in[9];
    const float* g2  = (const float*)d_in[10];
    const float* be2 = (const float*)d_in[11];
    const float* m2  = (const float*)d_in[12];
    const float* v2  = (const float*)d_in[13];
    const float* W3  = (const float*)d_in[14];
    const float* b3  = (const float*)d_in[15];
    float* out = (float*)d_out;

    split_feat_kernel<<<(Bsz * INF) / (256 * 4), 256>>>(feature);
    transpose_w1_kernel<<<dim3(H1D / 32, INF / 32, NO), dim3(32, 8)>>>(W1);
    transpose_w2_kernel<<<dim3(H2D / 32, H1D / 32, NO * NT), dim3(32, 8)>>>(W2);
    zero_counts_kernel<<<1, 32>>>();
    route_kernel<<<Bsz / 256, 256>>>(treatment);
    stage1_mma<<<dim3(H1D / 64, Bsz / 128, NO), 256>>>(b1, g1, be1, m1, v1);
    stage2_mma<<<dim3(Bsz / 128, NT * 4, NO), 256>>>(b2, g2, be2, m2, v2, W3);
    combine_kernel<<<(Bsz * NO) / 256, 256>>>(treatment, b3, out);
}